// round 3
// baseline (speedup 1.0000x reference)
#include <cuda_runtime.h>
#include <cuda_bf16.h>
#include <math.h>

// Problem constants
#define BB 32
#define TT_TOT 1500
#define SS 256
#define NMELS 80
#define TCH 512

// ---------------- scratch buffers (device globals; no allocation allowed) ---
__device__ float g_A[BB * 512 * SS];        // 4.19M
__device__ float g_Bf[BB * 512 * SS];       // 4.19M
__device__ float g_C[BB * 1024 * SS];       // 8.39M
__device__ float g_K[BB * 80 * SS];         // 0.66M
__device__ float g_D[BB * 160 * TT_TOT];    // 7.68M
__device__ float g_E[BB * 80 * TT_TOT];     // 3.84M
__device__ float g_Q[BB * 80 * TT_TOT];     // 3.84M
__device__ float g_k2[BB * SS];

// ---------------- embedding lookup: ph[b,c,s] = emb[idx[b,s], c] ------------
__global__ void embed_kernel(const int* __restrict__ ph,
                             const float* __restrict__ emb,
                             float* __restrict__ out) {
    int idx = blockIdx.x * blockDim.x + threadIdx.x;
    if (idx >= BB * 512 * SS) return;
    int s = idx & (SS - 1);
    int c = (idx >> 8) & 511;
    int b = idx >> 17;
    out[idx] = emb[ph[b * SS + s] * 512 + c];
}

// ---------------- generic tiled conv1d (SAME pad, odd K) --------------------
// x: [B, Cin, L], w: [Cout, Cin, K], y: [B, Cout, L]
// Block tile: 128 co x 64 s, 256 threads, 8x4 per-thread micro-tile,
// Cin chunked by 16 through shared memory.
template <int K, bool RELU>
__global__ __launch_bounds__(256) void conv1d_tiled(
    const float* __restrict__ x, const float* __restrict__ w,
    const float* __restrict__ bias, float* __restrict__ y,
    int Cin, int Cout, int L) {
    constexpr int PAD = K / 2;
    constexpr int TS = 64;
    constexpr int TCO = 128;
    constexpr int CC = 16;
    constexpr int XW = TS + K - 1;

    __shared__ float Xs[CC][XW];
    __shared__ float Ws[TCO][CC * K];

    const int b = blockIdx.z;
    const int s0 = blockIdx.x * TS;
    const int co0 = blockIdx.y * TCO;
    const int tid = threadIdx.x;
    const int tx = tid & 15;
    const int ty = tid >> 4;

    float acc[8][4];
#pragma unroll
    for (int i = 0; i < 8; i++)
#pragma unroll
        for (int j = 0; j < 4; j++) acc[i][j] = 0.f;

    const float* xb = x + (size_t)b * Cin * L;

    for (int ci0 = 0; ci0 < Cin; ci0 += CC) {
        // stage X tile (with zero padding at sequence edges)
        for (int i = tid; i < CC * XW; i += 256) {
            int cc = i / XW, sl = i % XW;
            int s = s0 + sl - PAD;
            Xs[cc][sl] = (s >= 0 && s < L) ? xb[(size_t)(ci0 + cc) * L + s] : 0.f;
        }
        // stage W tile: row co is 16*K contiguous floats in global w
        for (int i = tid; i < TCO * CC * K; i += 256) {
            int co = i / (CC * K), r = i % (CC * K);
            int gco = co0 + co;
            Ws[co][r] = (gco < Cout)
                            ? w[(size_t)gco * Cin * K + (size_t)ci0 * K + r]
                            : 0.f;
        }
        __syncthreads();

#pragma unroll
        for (int cc = 0; cc < CC; cc++) {
#pragma unroll
            for (int t = 0; t < K; t++) {
                float xv[4], wv[8];
#pragma unroll
                for (int j = 0; j < 4; j++) xv[j] = Xs[cc][tx + 16 * j + t];
#pragma unroll
                for (int i = 0; i < 8; i++) wv[i] = Ws[ty + 16 * i][cc * K + t];
#pragma unroll
                for (int i = 0; i < 8; i++)
#pragma unroll
                    for (int j = 0; j < 4; j++)
                        acc[i][j] = fmaf(wv[i], xv[j], acc[i][j]);
            }
        }
        __syncthreads();
    }

#pragma unroll
    for (int i = 0; i < 8; i++) {
        int co = co0 + ty + 16 * i;
        if (co >= Cout) continue;
        float bv = bias[co];
#pragma unroll
        for (int j = 0; j < 4; j++) {
            int s = s0 + tx + 16 * j;
            if (s >= L) continue;
            float v = acc[i][j] + bv;
            if (RELU) v = fmaxf(v, 0.f);
            y[((size_t)b * Cout + co) * L + s] = v;
        }
    }
}

// ---------------- k squared-norm: k2[b,s] = sum_c K[b,c,s]^2 ----------------
__global__ void k2_kernel(const float* __restrict__ k, float* __restrict__ k2) {
    int idx = blockIdx.x * blockDim.x + threadIdx.x;
    if (idx >= BB * SS) return;
    int s = idx & (SS - 1);
    int b = idx >> 8;
    const float* kp = k + (size_t)b * 80 * SS + s;
    float sum = 0.f;
#pragma unroll
    for (int c = 0; c < 80; c++) {
        float v = kp[(size_t)c * SS];
        sum = fmaf(v, v, sum);
    }
    k2[idx] = sum;
}

// ---------------- fused attention: qk GEMM + log_softmax + prior + mask -----
// Grid: (ceil(T/16), B). One thread per s in [0,256). 16 t-rows per block.
// logit = TEMP*(2*qk - k2)   (q2 row-constant cancels in log_softmax exactly)
// NOTE: mask arrives as int32 (harness materializes bool as int32).
__global__ __launch_bounds__(256) void attn_kernel(
    const float* __restrict__ q, const float* __restrict__ kbuf,
    const float* __restrict__ k2, const float* __restrict__ prior,
    const int* __restrict__ mask, float* __restrict__ out) {
    constexpr float TEMP = 0.0005f;
    __shared__ float Ks[16][SS];
    __shared__ float Qs[16][16];
    __shared__ float redM[8], redS[8];

    const int b = blockIdx.y;
    const int t0 = blockIdx.x * 16;
    const int s = threadIdx.x;

    float acc[16];
#pragma unroll
    for (int tt = 0; tt < 16; tt++) acc[tt] = 0.f;

    const float* qb = q + (size_t)b * 80 * TT_TOT;
    const float* kb = kbuf + (size_t)b * 80 * SS;

    for (int c0 = 0; c0 < 80; c0 += 16) {
        for (int i = threadIdx.x; i < 16 * SS; i += 256) {
            int cc = i >> 8, ss = i & (SS - 1);
            Ks[cc][ss] = kb[(size_t)(c0 + cc) * SS + ss];
        }
        {
            int cc = threadIdx.x >> 4, tt = threadIdx.x & 15;
            int t = t0 + tt;
            Qs[cc][tt] = (t < TT_TOT) ? qb[(size_t)(c0 + cc) * TT_TOT + t] : 0.f;
        }
        __syncthreads();
#pragma unroll
        for (int cc = 0; cc < 16; cc++) {
            float kv = Ks[cc][s];
#pragma unroll
            for (int tt = 0; tt < 16; tt++)
                acc[tt] = fmaf(Qs[cc][tt], kv, acc[tt]);
        }
        __syncthreads();
    }

    const float k2v = k2[b * SS + s];
    const int lane = s & 31, wid = s >> 5;

    for (int tt = 0; tt < 16; tt++) {
        int t = t0 + tt;
        if (t >= TT_TOT) break;  // uniform across block
        float a = TEMP * (2.f * acc[tt] - k2v);

        // online (max, sum-exp) warp reduction
        float m = a, se = 1.f;
#pragma unroll
        for (int o = 16; o; o >>= 1) {
            float m2 = __shfl_xor_sync(~0u, m, o);
            float s2 = __shfl_xor_sync(~0u, se, o);
            float M = fmaxf(m, m2);
            se = se * expf(m - M) + s2 * expf(m2 - M);
            m = M;
        }
        if (lane == 0) { redM[wid] = m; redS[wid] = se; }
        __syncthreads();
        float M = redM[0], SE = redS[0];
#pragma unroll
        for (int i = 1; i < 8; i++) {
            float mi = redM[i], si = redS[i];
            float Mn = fmaxf(M, mi);
            SE = SE * expf(M - Mn) + si * expf(mi - Mn);
            M = Mn;
        }
        float lse = M + logf(SE);
        __syncthreads();  // before next iteration's redM/redS writes

        size_t oidx = ((size_t)(b * TT_TOT + t)) * SS + s;
        float val = a - lse + logf(prior[oidx] + 1e-8f);
        out[oidx] = mask[oidx] ? val : -INFINITY;
    }
}

// ---------------- launch ----------------------------------------------------
extern "C" void kernel_launch(void* const* d_in, const int* in_sizes, int n_in,
                              void* d_out, int out_size) {
    const int* phonemes = (const int*)d_in[0];
    const float* mels = (const float*)d_in[1];
    const int* mask = (const int*)d_in[2];
    const float* prior = (const float*)d_in[3];
    const float* emb = (const float*)d_in[4];
    const float* kw0 = (const float*)d_in[5];
    const float* kb0 = (const float*)d_in[6];
    const float* kw1 = (const float*)d_in[7];
    const float* kb1 = (const float*)d_in[8];
    const float* kw2 = (const float*)d_in[9];
    const float* kb2 = (const float*)d_in[10];
    const float* kw3 = (const float*)d_in[11];
    const float* kb3 = (const float*)d_in[12];
    const float* kw4 = (const float*)d_in[13];
    const float* kb4 = (const float*)d_in[14];
    const float* qw0 = (const float*)d_in[15];
    const float* qb0 = (const float*)d_in[16];
    const float* qw1 = (const float*)d_in[17];
    const float* qb1 = (const float*)d_in[18];
    const float* qw2 = (const float*)d_in[19];
    const float* qb2 = (const float*)d_in[20];
    float* out = (float*)d_out;

    float *pA, *pB, *pC, *pK, *pD, *pE, *pQ, *pk2;
    cudaGetSymbolAddress((void**)&pA, g_A);
    cudaGetSymbolAddress((void**)&pB, g_Bf);
    cudaGetSymbolAddress((void**)&pC, g_C);
    cudaGetSymbolAddress((void**)&pK, g_K);
    cudaGetSymbolAddress((void**)&pD, g_D);
    cudaGetSymbolAddress((void**)&pE, g_E);
    cudaGetSymbolAddress((void**)&pQ, g_Q);
    cudaGetSymbolAddress((void**)&pk2, g_k2);

    // phoneme embedding -> [B, 512, S]
    embed_kernel<<<(BB * 512 * SS + 255) / 256, 256>>>(phonemes, emb, pA);

    // key encoder
    conv1d_tiled<5, true><<<dim3(4, 4, BB), 256>>>(pA, kw0, kb0, pB, 512, 512, SS);
    conv1d_tiled<5, true><<<dim3(4, 4, BB), 256>>>(pB, kw1, kb1, pA, 512, 512, SS);
    conv1d_tiled<5, true><<<dim3(4, 4, BB), 256>>>(pA, kw2, kb2, pB, 512, 512, SS);
    conv1d_tiled<3, true><<<dim3(4, 8, BB), 256>>>(pB, kw3, kb3, pC, 512, 1024, SS);
    conv1d_tiled<1, false><<<dim3(4, 1, BB), 256>>>(pC, kw4, kb4, pK, 1024, 80, SS);

    // query encoder
    conv1d_tiled<3, true><<<dim3(24, 2, BB), 256>>>(mels, qw0, qb0, pD, 80, 160, TT_TOT);
    conv1d_tiled<1, true><<<dim3(24, 1, BB), 256>>>(pD, qw1, qb1, pE, 160, 80, TT_TOT);
    conv1d_tiled<1, false><<<dim3(24, 1, BB), 256>>>(pE, qw2, qb2, pQ, 80, 80, TT_TOT);

    // k norms
    k2_kernel<<<(BB * SS + 255) / 256, 256>>>(pK, pk2);

    // fused attention + log_softmax + prior + mask
    attn_kernel<<<dim3((TT_TOT + 15) / 16, BB), 256>>>(pQ, pK, pk2, prior, mask, out);
}

// round 5
// speedup vs baseline: 3.2091x; 3.2091x over previous
#include <cuda_runtime.h>
#include <cuda_bf16.h>
#include <math.h>
#include <stdint.h>

// Problem constants
#define BB 32
#define TT_TOT 1500
#define SS 256

typedef __nv_bfloat16 bf16;

// ---------------- scratch buffers (device globals) --------------------------
__device__ __align__(16) bf16 g_act0[BB * 512 * SS];
__device__ __align__(16) bf16 g_act1[BB * 512 * SS];
__device__ __align__(16) bf16 g_bt[BB * SS * 2560];   // im2col B (K-major rows)
__device__ __align__(16) bf16 g_aw[1024 * 1536];      // repacked weights (max)
__device__ __align__(16) bf16 g_cb[BB * 1024 * SS];   // k3 conv out
__device__ float g_K[BB * 80 * SS];
__device__ float g_D[BB * 160 * TT_TOT];
__device__ float g_E[BB * 80 * TT_TOT];
__device__ float g_Q[BB * 80 * TT_TOT];
__device__ float g_k2v[BB * SS];

// ---------------- helpers ----------------------------------------------------
__device__ __forceinline__ uint32_t smem_u32(const void* p) {
    uint32_t a;
    asm("{ .reg .u64 t; cvta.to.shared.u64 t, %1; cvt.u32.u64 %0, t; }"
        : "=r"(a) : "l"(p));
    return a;
}
__device__ __forceinline__ void cp16(void* smem, const void* gmem) {
    asm volatile("cp.async.cg.shared.global [%0], [%1], 16;"
                 :: "r"(smem_u32(smem)), "l"(gmem) : "memory");
}
#define CP_COMMIT() asm volatile("cp.async.commit_group;" ::: "memory")
#define CP_WAIT0() asm volatile("cp.async.wait_group 0;" ::: "memory")

__device__ __forceinline__ void mma16816(float* d, const uint32_t* a,
                                         const uint32_t* b) {
    asm volatile(
        "mma.sync.aligned.m16n8k16.row.col.f32.bf16.bf16.f32 "
        "{%0,%1,%2,%3}, {%4,%5,%6,%7}, {%8,%9}, {%0,%1,%2,%3};"
        : "+f"(d[0]), "+f"(d[1]), "+f"(d[2]), "+f"(d[3])
        : "r"(a[0]), "r"(a[1]), "r"(a[2]), "r"(a[3]), "r"(b[0]), "r"(b[1]));
}

// ---------------- embedding lookup: act[b,c,s] = emb[idx[b,s], c] (bf16) ----
__global__ void embed_kernel(const int* __restrict__ ph,
                             const float* __restrict__ emb,
                             bf16* __restrict__ out) {
    int idx = blockIdx.x * blockDim.x + threadIdx.x;
    if (idx >= BB * 512 * SS) return;
    int s = idx & (SS - 1);
    int c = (idx >> 8) & 511;
    int b = idx >> 17;
    out[idx] = __float2bfloat16(emb[ph[b * SS + s] * 512 + c]);
}

// ---------------- weight repack: aw[co][t*Cin+ci] = w[co][ci][t] (bf16) -----
__global__ void prep_w(const float* __restrict__ w, bf16* __restrict__ aw,
                       int Cout, int Cin, int KT) {
    int o = blockIdx.x * 256 + threadIdx.x;
    int Kt = Cin * KT;
    if (o >= Cout * Kt) return;
    int co = o / Kt, rem = o - co * Kt;
    int t = rem / Cin, ci = rem - t * Cin;
    aw[o] = __float2bfloat16(w[(co * Cin + ci) * KT + t]);
}

// ---------------- im2col: bt[b][s][t*Cin+ci] = x[b][ci][s+t-PAD] ------------
template <int KT>
__global__ __launch_bounds__(256) void prep_b(const bf16* __restrict__ x,
                                              bf16* __restrict__ bt, int Cin) {
    constexpr int PAD = KT / 2;
    constexpr int W = 64 + KT - 1;
    __shared__ float xs[64][69];
    const int b = blockIdx.z;
    const int ci0 = blockIdx.y * 64;
    const int s0 = blockIdx.x * 64;
    const int Ktot = Cin * KT;
    for (int i = threadIdx.x; i < 64 * W; i += 256) {
        int ci = i / W, j = i - ci * W;
        int s = s0 + j - PAD;
        xs[ci][j] = (s >= 0 && s < SS)
                        ? __bfloat162float(x[((size_t)b * Cin + ci0 + ci) * SS + s])
                        : 0.f;
    }
    __syncthreads();
    for (int wk = threadIdx.x; wk < KT * 64 * 64; wk += 256) {
        int ci = wk & 63, s = (wk >> 6) & 63, t = wk >> 12;
        bt[((size_t)b * SS + s0 + s) * Ktot + t * Cin + ci0 + ci] =
            __float2bfloat16(xs[ci][s + t]);
    }
}

// ---------------- HMMA bf16 GEMM: Y = relu(Aw @ Bt^T + bias) ----------------
// Aw: [Cout, Ktot] bf16 K-major.  Bt: [B*S, Ktot] bf16 K-major.
// Block 128(co) x 128(s), 8 warps (2x4), warp tile 64x32, K chunk 32,
// cp.async double-buffered smem (rows padded to 40 bf16: conflict-free frags).
// Requires Cout % 128 == 0, Ktot % 32 == 0.  grid (SS/128, Cout/128, B)
template <bool RELU>
__global__ __launch_bounds__(256) void gemm_hmma(
    const bf16* __restrict__ Aw, const bf16* __restrict__ Bt,
    const float* __restrict__ bias, bf16* __restrict__ Y,
    int Ktot, int Cout) {
    constexpr int RP = 40;  // padded row length (bf16)
    __shared__ __align__(16) bf16 sA[2][128 * RP];
    __shared__ __align__(16) bf16 sB[2][128 * RP];

    const int tid = threadIdx.x;
    const int wid = tid >> 5, lane = tid & 31;
    const int wm = wid >> 2, wn = wid & 3;  // warp grid 2 x 4
    const int lr = lane >> 2, lc = (lane & 3) * 2;
    const int b = blockIdx.z, co0 = blockIdx.y * 128, s0 = blockIdx.x * 128;

    const bf16* gA = Aw + (size_t)co0 * Ktot;
    const bf16* gB = Bt + ((size_t)b * SS + s0) * Ktot;

    float acc[4][4][4];
#pragma unroll
    for (int i = 0; i < 4; i++)
#pragma unroll
        for (int j = 0; j < 4; j++)
#pragma unroll
            for (int v = 0; v < 4; v++) acc[i][j][v] = 0.f;

    const int nch = Ktot >> 5;

    // prologue: chunk 0 -> buffer 0
    {
#pragma unroll
        for (int n = 0; n < 2; n++) {
            int i = tid + n * 256;
            int row = i >> 2, u = i & 3;
            cp16(&sA[0][row * RP + u * 8], gA + (size_t)row * Ktot + u * 8);
            cp16(&sB[0][row * RP + u * 8], gB + (size_t)row * Ktot + u * 8);
        }
        CP_COMMIT();
    }

    for (int ch = 0; ch < nch; ch++) {
        CP_WAIT0();
        __syncthreads();
        if (ch + 1 < nch) {
            int nb = (ch + 1) & 1;
            int k0 = (ch + 1) * 32;
#pragma unroll
            for (int n = 0; n < 2; n++) {
                int i = tid + n * 256;
                int row = i >> 2, u = i & 3;
                cp16(&sA[nb][row * RP + u * 8],
                     gA + (size_t)row * Ktot + k0 + u * 8);
                cp16(&sB[nb][row * RP + u * 8],
                     gB + (size_t)row * Ktot + k0 + u * 8);
            }
            CP_COMMIT();
        }
        const bf16* Ab = sA[ch & 1];
        const bf16* Bb = sB[ch & 1];
#pragma unroll
        for (int kk = 0; kk < 2; kk++) {
            uint32_t af[4][4];
#pragma unroll
            for (int im = 0; im < 4; im++) {
                const bf16* p = Ab + (wm * 64 + im * 16 + lr) * RP + kk * 16 + lc;
                af[im][0] = *(const uint32_t*)p;
                af[im][1] = *(const uint32_t*)(p + 8 * RP);
                af[im][2] = *(const uint32_t*)(p + 8);
                af[im][3] = *(const uint32_t*)(p + 8 * RP + 8);
            }
            uint32_t bfr[4][2];
#pragma unroll
            for (int in = 0; in < 4; in++) {
                const bf16* p = Bb + (wn * 32 + in * 8 + lr) * RP + kk * 16 + lc;
                bfr[in][0] = *(const uint32_t*)p;
                bfr[in][1] = *(const uint32_t*)(p + 8);
            }
#pragma unroll
            for (int im = 0; im < 4; im++)
#pragma unroll
                for (int in = 0; in < 4; in++)
                    mma16816(acc[im][in], af[im], bfr[in]);
        }
        __syncthreads();
    }

    // epilogue: bias (+relu) -> bf16x2 stores
#pragma unroll
    for (int im = 0; im < 4; im++) {
        int co = co0 + wm * 64 + im * 16 + lr;
        float b0v = bias[co], b1v = bias[co + 8];
#pragma unroll
        for (int in = 0; in < 4; in++) {
            int s = s0 + wn * 32 + in * 8 + lc;
            float* d = acc[im][in];
            float v0 = d[0] + b0v, v1 = d[1] + b0v;
            float v2 = d[2] + b1v, v3 = d[3] + b1v;
            if (RELU) {
                v0 = fmaxf(v0, 0.f); v1 = fmaxf(v1, 0.f);
                v2 = fmaxf(v2, 0.f); v3 = fmaxf(v3, 0.f);
            }
            __nv_bfloat162 p0; p0.x = __float2bfloat16(v0); p0.y = __float2bfloat16(v1);
            __nv_bfloat162 p1; p1.x = __float2bfloat16(v2); p1.y = __float2bfloat16(v3);
            *(__nv_bfloat162*)&Y[((size_t)b * Cout + co) * SS + s] = p0;
            *(__nv_bfloat162*)&Y[((size_t)b * Cout + co + 8) * SS + s] = p1;
        }
    }
}

// ---------------- generic tiled conv1d (FFMA; k1 + query path) --------------
__device__ __forceinline__ float ld_as_f(const float* p) { return *p; }
__device__ __forceinline__ float ld_as_f(const bf16* p) { return __bfloat162float(*p); }

template <int K, bool RELU, typename TIN>
__global__ __launch_bounds__(256) void conv1d_tiled(
    const TIN* __restrict__ x, const float* __restrict__ w,
    const float* __restrict__ bias, float* __restrict__ y,
    int Cin, int Cout, int L) {
    constexpr int PAD = K / 2;
    constexpr int TS = 64;
    constexpr int TCO = 128;
    constexpr int CC = 16;
    constexpr int XW = TS + K - 1;

    __shared__ float Xs[CC][XW];
    __shared__ float Ws[TCO][CC * K];

    const int b = blockIdx.z;
    const int s0 = blockIdx.x * TS;
    const int co0 = blockIdx.y * TCO;
    const int tid = threadIdx.x;
    const int tx = tid & 15;
    const int ty = tid >> 4;

    float acc[8][4];
#pragma unroll
    for (int i = 0; i < 8; i++)
#pragma unroll
        for (int j = 0; j < 4; j++) acc[i][j] = 0.f;

    const TIN* xb = x + (size_t)b * Cin * L;

    for (int ci0 = 0; ci0 < Cin; ci0 += CC) {
        for (int i = tid; i < CC * XW; i += 256) {
            int cc = i / XW, sl = i % XW;
            int s = s0 + sl - PAD;
            Xs[cc][sl] = (s >= 0 && s < L) ? ld_as_f(xb + (size_t)(ci0 + cc) * L + s) : 0.f;
        }
        for (int i = tid; i < TCO * CC * K; i += 256) {
            int co = i / (CC * K), r = i % (CC * K);
            int gco = co0 + co;
            Ws[co][r] = (gco < Cout)
                            ? w[(size_t)gco * Cin * K + (size_t)ci0 * K + r]
                            : 0.f;
        }
        __syncthreads();

#pragma unroll
        for (int cc = 0; cc < CC; cc++) {
#pragma unroll
            for (int t = 0; t < K; t++) {
                float xv[4], wv[8];
#pragma unroll
                for (int j = 0; j < 4; j++) xv[j] = Xs[cc][tx + 16 * j + t];
#pragma unroll
                for (int i = 0; i < 8; i++) wv[i] = Ws[ty + 16 * i][cc * K + t];
#pragma unroll
                for (int i = 0; i < 8; i++)
#pragma unroll
                    for (int j = 0; j < 4; j++)
                        acc[i][j] = fmaf(wv[i], xv[j], acc[i][j]);
            }
        }
        __syncthreads();
    }

#pragma unroll
    for (int i = 0; i < 8; i++) {
        int co = co0 + ty + 16 * i;
        if (co >= Cout) continue;
        float bv = bias[co];
#pragma unroll
        for (int j = 0; j < 4; j++) {
            int s = s0 + tx + 16 * j;
            if (s >= L) continue;
            float v = acc[i][j] + bv;
            if (RELU) v = fmaxf(v, 0.f);
            y[((size_t)b * Cout + co) * L + s] = v;
        }
    }
}

// ---------------- k squared-norm --------------------------------------------
__global__ void k2_kernel(const float* __restrict__ k, float* __restrict__ k2) {
    int idx = blockIdx.x * blockDim.x + threadIdx.x;
    if (idx >= BB * SS) return;
    int s = idx & (SS - 1);
    int b = idx >> 8;
    const float* kp = k + (size_t)b * 80 * SS + s;
    float sum = 0.f;
#pragma unroll
    for (int c = 0; c < 80; c++) {
        float v = kp[(size_t)c * SS];
        sum = fmaf(v, v, sum);
    }
    k2[idx] = sum;
}

// ---------------- fused attention: qk + log_softmax + prior + mask ----------
__global__ __launch_bounds__(256) void attn_kernel(
    const float* __restrict__ q, const float* __restrict__ kbuf,
    const float* __restrict__ k2, const float* __restrict__ prior,
    const int* __restrict__ mask, float* __restrict__ out) {
    constexpr float TEMP = 0.0005f;
    __shared__ float Ks[16][SS];
    __shared__ float Qs[16][16];
    __shared__ float redM[8], redS[8];

    const int b = blockIdx.y;
    const int t0 = blockIdx.x * 16;
    const int s = threadIdx.x;

    float acc[16];
#pragma unroll
    for (int tt = 0; tt < 16; tt++) acc[tt] = 0.f;

    const float* qb = q + (size_t)b * 80 * TT_TOT;
    const float* kb = kbuf + (size_t)b * 80 * SS;

    for (int c0 = 0; c0 < 80; c0 += 16) {
        for (int i = threadIdx.x; i < 16 * SS; i += 256) {
            int cc = i >> 8, ss = i & (SS - 1);
            Ks[cc][ss] = kb[(size_t)(c0 + cc) * SS + ss];
        }
        {
            int cc = threadIdx.x >> 4, tt = threadIdx.x & 15;
            int t = t0 + tt;
            Qs[cc][tt] = (t < TT_TOT) ? qb[(size_t)(c0 + cc) * TT_TOT + t] : 0.f;
        }
        __syncthreads();
#pragma unroll
        for (int cc = 0; cc < 16; cc++) {
            float kv = Ks[cc][s];
#pragma unroll
            for (int tt = 0; tt < 16; tt++)
                acc[tt] = fmaf(Qs[cc][tt], kv, acc[tt]);
        }
        __syncthreads();
    }

    const float k2v = k2[b * SS + s];
    const int lane = s & 31, wid = s >> 5;

    for (int tt = 0; tt < 16; tt++) {
        int t = t0 + tt;
        if (t >= TT_TOT) break;
        float a = TEMP * (2.f * acc[tt] - k2v);

        float m = a, se = 1.f;
#pragma unroll
        for (int o = 16; o; o >>= 1) {
            float m2 = __shfl_xor_sync(~0u, m, o);
            float s2 = __shfl_xor_sync(~0u, se, o);
            float M = fmaxf(m, m2);
            se = se * expf(m - M) + s2 * expf(m2 - M);
            m = M;
        }
        if (lane == 0) { redM[wid] = m; redS[wid] = se; }
        __syncthreads();
        float M = redM[0], SE = redS[0];
#pragma unroll
        for (int i = 1; i < 8; i++) {
            float mi = redM[i], si = redS[i];
            float Mn = fmaxf(M, mi);
            SE = SE * expf(M - Mn) + si * expf(mi - Mn);
            M = Mn;
        }
        float lse = M + logf(SE);
        __syncthreads();

        size_t oidx = ((size_t)(b * TT_TOT + t)) * SS + s;
        float val = a - lse + logf(prior[oidx] + 1e-8f);
        out[oidx] = mask[oidx] ? val : -INFINITY;
    }
}

// ---------------- launch ----------------------------------------------------
extern "C" void kernel_launch(void* const* d_in, const int* in_sizes, int n_in,
                              void* d_out, int out_size) {
    const int* phonemes = (const int*)d_in[0];
    const float* mels = (const float*)d_in[1];
    const int* mask = (const int*)d_in[2];
    const float* prior = (const float*)d_in[3];
    const float* emb = (const float*)d_in[4];
    const float* kw0 = (const float*)d_in[5];
    const float* kb0 = (const float*)d_in[6];
    const float* kw1 = (const float*)d_in[7];
    const float* kb1 = (const float*)d_in[8];
    const float* kw2 = (const float*)d_in[9];
    const float* kb2 = (const float*)d_in[10];
    const float* kw3 = (const float*)d_in[11];
    const float* kb3 = (const float*)d_in[12];
    const float* kw4 = (const float*)d_in[13];
    const float* kb4 = (const float*)d_in[14];
    const float* qw0 = (const float*)d_in[15];
    const float* qb0 = (const float*)d_in[16];
    const float* qw1 = (const float*)d_in[17];
    const float* qb1 = (const float*)d_in[18];
    const float* qw2 = (const float*)d_in[19];
    const float* qb2 = (const float*)d_in[20];
    float* out = (float*)d_out;

    bf16 *pAct0, *pAct1, *pBt, *pAw, *pCb;
    float *pK, *pD, *pE, *pQ, *pk2;
    cudaGetSymbolAddress((void**)&pAct0, g_act0);
    cudaGetSymbolAddress((void**)&pAct1, g_act1);
    cudaGetSymbolAddress((void**)&pBt, g_bt);
    cudaGetSymbolAddress((void**)&pAw, g_aw);
    cudaGetSymbolAddress((void**)&pCb, g_cb);
    cudaGetSymbolAddress((void**)&pK, g_K);
    cudaGetSymbolAddress((void**)&pD, g_D);
    cudaGetSymbolAddress((void**)&pE, g_E);
    cudaGetSymbolAddress((void**)&pQ, g_Q);
    cudaGetSymbolAddress((void**)&pk2, g_k2v);

    // phoneme embedding -> bf16 [B, 512, S]
    embed_kernel<<<(BB * 512 * SS + 255) / 256, 256>>>(phonemes, emb, pAct0);

    // ---- key encoder: HMMA GEMMs ----
    prep_w<<<(512 * 2560 + 255) / 256, 256>>>(kw0, pAw, 512, 512, 5);
    prep_b<5><<<dim3(4, 8, BB), 256>>>(pAct0, pBt, 512);
    gemm_hmma<true><<<dim3(2, 4, BB), 256>>>(pAw, pBt, kb0, pAct1, 2560, 512);

    prep_w<<<(512 * 2560 + 255) / 256, 256>>>(kw1, pAw, 512, 512, 5);
    prep_b<5><<<dim3(4, 8, BB), 256>>>(pAct1, pBt, 512);
    gemm_hmma<true><<<dim3(2, 4, BB), 256>>>(pAw, pBt, kb1, pAct0, 2560, 512);

    prep_w<<<(512 * 2560 + 255) / 256, 256>>>(kw2, pAw, 512, 512, 5);
    prep_b<5><<<dim3(4, 8, BB), 256>>>(pAct0, pBt, 512);
    gemm_hmma<true><<<dim3(2, 4, BB), 256>>>(pAw, pBt, kb2, pAct1, 2560, 512);

    prep_w<<<(1024 * 1536 + 255) / 256, 256>>>(kw3, pAw, 1024, 512, 3);
    prep_b<3><<<dim3(4, 8, BB), 256>>>(pAct1, pBt, 512);
    gemm_hmma<true><<<dim3(2, 8, BB), 256>>>(pAw, pBt, kb3, pCb, 1536, 1024);

    // layer 4: 1024->80 k1 (FFMA, bf16 input)
    conv1d_tiled<1, false, bf16><<<dim3(4, 1, BB), 256>>>(pCb, kw4, kb4, pK, 1024, 80, SS);

    // ---- query encoder (FFMA, fp32) ----
    conv1d_tiled<3, true, float><<<dim3(24, 2, BB), 256>>>(mels, qw0, qb0, pD, 80, 160, TT_TOT);
    conv1d_tiled<1, true, float><<<dim3(24, 1, BB), 256>>>(pD, qw1, qb1, pE, 160, 80, TT_TOT);
    conv1d_tiled<1, false, float><<<dim3(24, 1, BB), 256>>>(pE, qw2, qb2, pQ, 80, 80, TT_TOT);

    // k norms
    k2_kernel<<<(BB * SS + 255) / 256, 256>>>(pK, pk2);

    // fused attention + log_softmax + prior + mask
    attn_kernel<<<dim3((TT_TOT + 15) / 16, BB), 256>>>(pQ, pK, pk2, prior, mask, out);
}

// round 6
// speedup vs baseline: 5.2640x; 1.6403x over previous
#include <cuda_runtime.h>
#include <cuda_bf16.h>
#include <math.h>
#include <stdint.h>

#define BB 32
#define TT_TOT 1500
#define SS 256

typedef __nv_bfloat16 bf16;

// ---------------- scratch buffers (device globals) --------------------------
__device__ __align__(16) bf16 g_actT0[BB * SS * 512];
__device__ __align__(16) bf16 g_actT1[BB * SS * 512];
__device__ __align__(16) bf16 g_cT[BB * SS * 1024];
__device__ __align__(16) bf16 g_kT[BB * SS * 96];
__device__ __align__(16) bf16 g_melsT[BB * TT_TOT * 96];
__device__ __align__(16) bf16 g_q0T[(size_t)BB * TT_TOT * 192];
__device__ __align__(16) bf16 g_q1T[(size_t)BB * TT_TOT * 128];
__device__ __align__(16) bf16 g_q2T[BB * TT_TOT * 96];
__device__ __align__(16) bf16 g_aw[1024 * 1536];
__device__ float g_k2v[BB * SS];
__device__ __align__(16) bf16 g_zero[8];  // zero-initialized

// ---------------- helpers ----------------------------------------------------
__device__ __forceinline__ uint32_t smem_u32(const void* p) {
    uint32_t a;
    asm("{ .reg .u64 t; cvta.to.shared.u64 t, %1; cvt.u32.u64 %0, t; }"
        : "=r"(a) : "l"(p));
    return a;
}
__device__ __forceinline__ void cp16(void* smem, const void* gmem) {
    asm volatile("cp.async.cg.shared.global [%0], [%1], 16;"
                 :: "r"(smem_u32(smem)), "l"(gmem) : "memory");
}
#define CP_COMMIT() asm volatile("cp.async.commit_group;" ::: "memory")
#define CP_WAIT0() asm volatile("cp.async.wait_group 0;" ::: "memory")

__device__ __forceinline__ void mma16816(float* d, const uint32_t* a,
                                         const uint32_t* b) {
    asm volatile(
        "mma.sync.aligned.m16n8k16.row.col.f32.bf16.bf16.f32 "
        "{%0,%1,%2,%3}, {%4,%5,%6,%7}, {%8,%9}, {%0,%1,%2,%3};"
        : "+f"(d[0]), "+f"(d[1]), "+f"(d[2]), "+f"(d[3])
        : "r"(a[0]), "r"(a[1]), "r"(a[2]), "r"(a[3]), "r"(b[0]), "r"(b[1]));
}

// ---------------- embedding: actT[b][s][c] = emb[idx[b,s], c] (bf16) --------
__global__ void embed_kernel(const int* __restrict__ ph,
                             const float* __restrict__ emb,
                             bf16* __restrict__ out) {
    int idx = blockIdx.x * blockDim.x + threadIdx.x;
    if (idx >= BB * SS * 512) return;
    int c = idx & 511;
    int s = (idx >> 9) & (SS - 1);
    int b = idx >> 17;
    out[idx] = __float2bfloat16(emb[ph[b * SS + s] * 512 + c]);
}

// ------- weight repack: aw[co][t*CINP+ci] = w[co][ci][t], zero-padded -------
__global__ void prep_w(const float* __restrict__ w, bf16* __restrict__ aw,
                       int Cout, int Cin, int KT, int CINP, int rowsPad) {
    int Ktot = KT * CINP;
    int idx = blockIdx.x * 256 + threadIdx.x;
    if (idx >= rowsPad * Ktot) return;
    int co = idx / Ktot, k = idx - co * Ktot;
    int t = k / CINP, ci = k - t * CINP;
    aw[idx] = __float2bfloat16(
        (co < Cout && ci < Cin) ? w[(co * Cin + ci) * KT + t] : 0.f);
}

// ------- mels transpose: melsT[b][t][ci] (bf16, ci padded to 96) ------------
__global__ __launch_bounds__(256) void melsT_kernel(const float* __restrict__ mels,
                                                    bf16* __restrict__ melsT) {
    __shared__ float tile[32][33];
    const int b = blockIdx.z;
    const int c0 = blockIdx.y * 32;
    const int t0 = blockIdx.x * 32;
    const int tx = threadIdx.x & 31, ty = threadIdx.x >> 5;
#pragma unroll
    for (int p = 0; p < 4; p++) {
        int c = ty + p * 8;
        tile[c][tx] = (c0 + c < 80 && t0 + tx < TT_TOT)
                          ? mels[((size_t)b * 80 + c0 + c) * TT_TOT + t0 + tx]
                          : 0.f;
    }
    __syncthreads();
#pragma unroll
    for (int p = 0; p < 4; p++) {
        int t = ty + p * 8;
        if (t0 + t < TT_TOT)
            melsT[((size_t)b * TT_TOT + t0 + t) * 96 + c0 + tx] =
                __float2bfloat16(tile[tx][t]);
    }
}

// ---------------- fused conv-as-GEMM (HMMA bf16) ----------------------------
// out[b][s][co] = act(bias[co] + sum_{t,ci} Aw[co][t*CINP+ci] * actT[b][s+t-P][ci])
// Block 128co x 128s, 8 warps 2x4, warp tile 64x32, K chunk 32, double-buffer.
template <int KT, int CINP, bool RELU>
__global__ __launch_bounds__(256) void gemm_conv(
    const bf16* __restrict__ Aw, const bf16* __restrict__ actT,
    const float* __restrict__ bias, bf16* __restrict__ outT,
    int Cout, int CS, int L) {
    constexpr int KTOT = KT * CINP;
    constexpr int NCH = KTOT / 32;
    constexpr int PAD = KT / 2;
    constexpr int RP = 40;
    __shared__ __align__(16) bf16 sA[2][128 * RP];
    __shared__ __align__(16) bf16 sB[2][128 * RP];

    const int tid = threadIdx.x;
    const int wid = tid >> 5, lane = tid & 31;
    const int wm = wid >> 2, wn = wid & 3;
    const int lr = lane >> 2, lc = (lane & 3) * 2;
    const int b = blockIdx.z, co0 = blockIdx.y * 128, s0 = blockIdx.x * 128;

    const bf16* gA = Aw + (size_t)co0 * KTOT;
    const bf16* actB = actT + (size_t)b * L * CINP;

    float acc[4][4][4];
#pragma unroll
    for (int i = 0; i < 4; i++)
#pragma unroll
        for (int j = 0; j < 4; j++)
#pragma unroll
            for (int v = 0; v < 4; v++) acc[i][j][v] = 0.f;

    auto load_chunk = [&](int buf, int ch) {
        const int k0 = ch * 32;
#pragma unroll
        for (int n = 0; n < 2; n++) {
            int i = tid + n * 256;
            int row = i >> 2, u = i & 3;
            cp16(&sA[buf][row * RP + u * 8],
                 gA + (size_t)row * KTOT + k0 + u * 8);
        }
#pragma unroll
        for (int n = 0; n < 2; n++) {
            int i = tid + n * 256;
            int row = i >> 2, u = i & 3;
            int k = k0 + u * 8;
            int t = k / CINP;
            int ci = k - t * CINP;
            int gs = s0 + row + t - PAD;
            const bf16* src = (gs >= 0 && gs < L)
                                  ? actB + (size_t)gs * CINP + ci
                                  : g_zero;
            cp16(&sB[buf][row * RP + u * 8], src);
        }
        CP_COMMIT();
    };

    load_chunk(0, 0);

    for (int ch = 0; ch < NCH; ch++) {
        CP_WAIT0();
        __syncthreads();
        if (ch + 1 < NCH) load_chunk((ch + 1) & 1, ch + 1);
        const bf16* Ab = sA[ch & 1];
        const bf16* Bb = sB[ch & 1];
#pragma unroll
        for (int kk = 0; kk < 2; kk++) {
            uint32_t af[4][4];
#pragma unroll
            for (int im = 0; im < 4; im++) {
                const bf16* p = Ab + (wm * 64 + im * 16 + lr) * RP + kk * 16 + lc;
                af[im][0] = *(const uint32_t*)p;
                af[im][1] = *(const uint32_t*)(p + 8 * RP);
                af[im][2] = *(const uint32_t*)(p + 8);
                af[im][3] = *(const uint32_t*)(p + 8 * RP + 8);
            }
            uint32_t bfr[4][2];
#pragma unroll
            for (int in = 0; in < 4; in++) {
                const bf16* p = Bb + (wn * 32 + in * 8 + lr) * RP + kk * 16 + lc;
                bfr[in][0] = *(const uint32_t*)p;
                bfr[in][1] = *(const uint32_t*)(p + 8);
            }
#pragma unroll
            for (int im = 0; im < 4; im++)
#pragma unroll
                for (int in = 0; in < 4; in++)
                    mma16816(acc[im][in], af[im], bfr[in]);
        }
        __syncthreads();
    }

    // transposed epilogue: acc -> ep[s][co] (bf16) -> coalesced stores
    bf16* ep = (bf16*)sA;  // 128 x 72 bf16
#pragma unroll
    for (int c = 0; c < 2; c++) {
        if (wm == c) {
#pragma unroll
            for (int im = 0; im < 4; im++) {
                int co_loc = im * 16 + lr;
                int gco = co0 + c * 64 + co_loc;
                float b0v = (gco < Cout) ? bias[gco] : 0.f;
                float b1v = (gco + 8 < Cout) ? bias[gco + 8] : 0.f;
#pragma unroll
                for (int in = 0; in < 4; in++) {
                    int sl = wn * 32 + in * 8 + lc;
                    float* d = acc[im][in];
                    float v0 = d[0] + b0v, v1 = d[1] + b0v;
                    float v2 = d[2] + b1v, v3 = d[3] + b1v;
                    if (RELU) {
                        v0 = fmaxf(v0, 0.f); v1 = fmaxf(v1, 0.f);
                        v2 = fmaxf(v2, 0.f); v3 = fmaxf(v3, 0.f);
                    }
                    ep[sl * 72 + co_loc] = __float2bfloat16(v0);
                    ep[(sl + 1) * 72 + co_loc] = __float2bfloat16(v1);
                    ep[sl * 72 + co_loc + 8] = __float2bfloat16(v2);
                    ep[(sl + 1) * 72 + co_loc + 8] = __float2bfloat16(v3);
                }
            }
        }
        __syncthreads();
        int w = CS - (co0 + c * 64);
        if (w > 64) w = 64;
        if (w > 0) {
            int vpr = w >> 3;
            int tot = 128 * vpr;
            for (int idx = tid; idx < tot; idx += 256) {
                int s = idx / vpr, v = idx - s * vpr;
                if (s0 + s < L)
                    *(uint4*)(outT + ((size_t)b * L + s0 + s) * CS + co0 +
                              c * 64 + v * 8) = *(const uint4*)(ep + s * 72 + v * 8);
            }
        }
        __syncthreads();
    }
}

// ---------------- k squared-norm from kT [b][s][96] -------------------------
__global__ void k2_kernel(const bf16* __restrict__ kT, float* __restrict__ k2) {
    int idx = blockIdx.x * blockDim.x + threadIdx.x;
    if (idx >= BB * SS) return;
    const bf16* p = kT + (size_t)idx * 96;
    float sum = 0.f;
#pragma unroll
    for (int c = 0; c < 96; c++) {
        float v = __bfloat162float(p[c]);
        sum = fmaf(v, v, sum);
    }
    k2[idx] = sum;
}

// ---------------- fused attention: qk + log_softmax + prior + mask ----------
__global__ __launch_bounds__(256) void attn_kernel(
    const bf16* __restrict__ q2T, const bf16* __restrict__ kT,
    const float* __restrict__ k2, const float* __restrict__ prior,
    const int* __restrict__ mask, float* __restrict__ out) {
    constexpr float TEMP = 0.0005f;
    __shared__ float Ks[SS][17];
    __shared__ float Qs[16][16];
    __shared__ float redM[8], redS[8];

    const int b = blockIdx.y;
    const int t0 = blockIdx.x * 16;
    const int s = threadIdx.x;

    float acc[16];
#pragma unroll
    for (int tt = 0; tt < 16; tt++) acc[tt] = 0.f;

    for (int c0 = 0; c0 < 80; c0 += 16) {
        for (int i = threadIdx.x; i < SS * 16; i += 256) {
            int ss = i >> 4, cc = i & 15;
            Ks[ss][cc] =
                __bfloat162float(kT[((size_t)b * SS + ss) * 96 + c0 + cc]);
        }
        {
            int cc = threadIdx.x >> 4, tt = threadIdx.x & 15;
            int t = t0 + tt;
            Qs[cc][tt] = (t < TT_TOT)
                             ? __bfloat162float(
                                   q2T[((size_t)b * TT_TOT + t) * 96 + c0 + cc])
                             : 0.f;
        }
        __syncthreads();
#pragma unroll
        for (int cc = 0; cc < 16; cc++) {
            float kv = Ks[s][cc];
#pragma unroll
            for (int tt = 0; tt < 16; tt++)
                acc[tt] = fmaf(Qs[cc][tt], kv, acc[tt]);
        }
        __syncthreads();
    }

    const float k2v = k2[b * SS + s];
    const int lane = s & 31, wid = s >> 5;

    for (int tt = 0; tt < 16; tt++) {
        int t = t0 + tt;
        if (t >= TT_TOT) break;
        float a = TEMP * (2.f * acc[tt] - k2v);

        float m = a, se = 1.f;
#pragma unroll
        for (int o = 16; o; o >>= 1) {
            float m2 = __shfl_xor_sync(~0u, m, o);
            float s2 = __shfl_xor_sync(~0u, se, o);
            float M = fmaxf(m, m2);
            se = se * expf(m - M) + s2 * expf(m2 - M);
            m = M;
        }
        if (lane == 0) { redM[wid] = m; redS[wid] = se; }
        __syncthreads();
        float M = redM[0], SE = redS[0];
#pragma unroll
        for (int i = 1; i < 8; i++) {
            float mi = redM[i], si = redS[i];
            float Mn = fmaxf(M, mi);
            SE = SE * expf(M - Mn) + si * expf(mi - Mn);
            M = Mn;
        }
        float lse = M + logf(SE);
        __syncthreads();

        size_t oidx = ((size_t)(b * TT_TOT + t)) * SS + s;
        float val = a - lse + logf(prior[oidx] + 1e-8f);
        out[oidx] = mask[oidx] ? val : -INFINITY;
    }
}

// ---------------- launch ----------------------------------------------------
extern "C" void kernel_launch(void* const* d_in, const int* in_sizes, int n_in,
                              void* d_out, int out_size) {
    const int* phonemes = (const int*)d_in[0];
    const float* mels = (const float*)d_in[1];
    const int* mask = (const int*)d_in[2];
    const float* prior = (const float*)d_in[3];
    const float* emb = (const float*)d_in[4];
    const float* kw0 = (const float*)d_in[5];
    const float* kb0 = (const float*)d_in[6];
    const float* kw1 = (const float*)d_in[7];
    const float* kb1 = (const float*)d_in[8];
    const float* kw2 = (const float*)d_in[9];
    const float* kb2 = (const float*)d_in[10];
    const float* kw3 = (const float*)d_in[11];
    const float* kb3 = (const float*)d_in[12];
    const float* kw4 = (const float*)d_in[13];
    const float* kb4 = (const float*)d_in[14];
    const float* qw0 = (const float*)d_in[15];
    const float* qb0 = (const float*)d_in[16];
    const float* qw1 = (const float*)d_in[17];
    const float* qb1 = (const float*)d_in[18];
    const float* qw2 = (const float*)d_in[19];
    const float* qb2 = (const float*)d_in[20];
    float* out = (float*)d_out;

    bf16 *pA0, *pA1, *pCT, *pKT, *pMT, *pQ0, *pQ1, *pQ2, *pAw;
    float* pk2;
    cudaGetSymbolAddress((void**)&pA0, g_actT0);
    cudaGetSymbolAddress((void**)&pA1, g_actT1);
    cudaGetSymbolAddress((void**)&pCT, g_cT);
    cudaGetSymbolAddress((void**)&pKT, g_kT);
    cudaGetSymbolAddress((void**)&pMT, g_melsT);
    cudaGetSymbolAddress((void**)&pQ0, g_q0T);
    cudaGetSymbolAddress((void**)&pQ1, g_q1T);
    cudaGetSymbolAddress((void**)&pQ2, g_q2T);
    cudaGetSymbolAddress((void**)&pAw, g_aw);
    cudaGetSymbolAddress((void**)&pk2, g_k2v);

    // embedding -> actT0 [b][s][512]
    embed_kernel<<<(BB * SS * 512 + 255) / 256, 256>>>(phonemes, emb, pA0);

    // ---- key encoder ----
    prep_w<<<(512 * 2560 + 255) / 256, 256>>>(kw0, pAw, 512, 512, 5, 512, 512);
    gemm_conv<5, 512, true><<<dim3(2, 4, BB), 256>>>(pAw, pA0, kb0, pA1, 512, 512, SS);
    prep_w<<<(512 * 2560 + 255) / 256, 256>>>(kw1, pAw, 512, 512, 5, 512, 512);
    gemm_conv<5, 512, true><<<dim3(2, 4, BB), 256>>>(pAw, pA1, kb1, pA0, 512, 512, SS);
    prep_w<<<(512 * 2560 + 255) / 256, 256>>>(kw2, pAw, 512, 512, 5, 512, 512);
    gemm_conv<5, 512, true><<<dim3(2, 4, BB), 256>>>(pAw, pA0, kb2, pA1, 512, 512, SS);
    prep_w<<<(1024 * 1536 + 255) / 256, 256>>>(kw3, pAw, 1024, 512, 3, 512, 1024);
    gemm_conv<3, 512, true><<<dim3(2, 8, BB), 256>>>(pAw, pA1, kb3, pCT, 1024, 1024, SS);
    prep_w<<<(128 * 1024 + 255) / 256, 256>>>(kw4, pAw, 80, 1024, 1, 1024, 128);
    gemm_conv<1, 1024, false><<<dim3(2, 1, BB), 256>>>(pAw, pCT, kb4, pKT, 80, 96, SS);

    // k norms
    k2_kernel<<<(BB * SS + 255) / 256, 256>>>(pKT, pk2);

    // ---- query encoder ----
    melsT_kernel<<<dim3(47, 3, BB), 256>>>(mels, pMT);
    prep_w<<<(256 * 288 + 255) / 256, 256>>>(qw0, pAw, 160, 80, 3, 96, 256);
    gemm_conv<3, 96, true><<<dim3(12, 2, BB), 256>>>(pAw, pMT, qb0, pQ0, 160, 192, TT_TOT);
    prep_w<<<(128 * 192 + 255) / 256, 256>>>(qw1, pAw, 80, 160, 1, 192, 128);
    gemm_conv<1, 192, true><<<dim3(12, 1, BB), 256>>>(pAw, pQ0, qb1, pQ1, 80, 128, TT_TOT);
    prep_w<<<(128 * 128 + 255) / 256, 256>>>(qw2, pAw, 80, 80, 1, 128, 128);
    gemm_conv<1, 128, false><<<dim3(12, 1, BB), 256>>>(pAw, pQ1, qb2, pQ2, 80, 96, TT_TOT);

    // fused attention + log_softmax + prior + mask
    attn_kernel<<<dim3((TT_TOT + 15) / 16, BB), 256>>>(pQ2, pKT, pk2, prior, mask, out);
}

// round 7
// speedup vs baseline: 6.7078x; 1.2743x over previous
#include <cuda_runtime.h>
#include <cuda_bf16.h>
#include <math.h>
#include <stdint.h>

#define BB 32
#define TT_TOT 1500
#define SS 256

typedef __nv_bfloat16 bf16;

// ---------------- scratch buffers (device globals) --------------------------
__device__ __align__(16) bf16 g_actT0[BB * SS * 512];
__device__ __align__(16) bf16 g_actT1[BB * SS * 512];
__device__ __align__(16) bf16 g_cT[BB * SS * 1024];
__device__ __align__(16) bf16 g_kT[BB * SS * 96];
__device__ __align__(16) bf16 g_melsT[BB * TT_TOT * 96];
__device__ __align__(16) bf16 g_q0T[(size_t)BB * TT_TOT * 192];
__device__ __align__(16) bf16 g_q1T[(size_t)BB * TT_TOT * 128];
__device__ __align__(16) bf16 g_q2T[BB * TT_TOT * 96];
// per-layer repacked weights
__device__ __align__(16) bf16 g_w0[512 * 2560];
__device__ __align__(16) bf16 g_w1[512 * 2560];
__device__ __align__(16) bf16 g_w2[512 * 2560];
__device__ __align__(16) bf16 g_w3[1024 * 1536];
__device__ __align__(16) bf16 g_w4[128 * 1024];
__device__ __align__(16) bf16 g_wq0[256 * 288];
__device__ __align__(16) bf16 g_wq1[128 * 192];
__device__ __align__(16) bf16 g_wq2[128 * 128];
__device__ float g_k2v[BB * SS];
__device__ __align__(16) bf16 g_zero[8];  // zero page

// ---------------- helpers ----------------------------------------------------
__device__ __forceinline__ uint32_t smem_u32(const void* p) {
    uint32_t a;
    asm("{ .reg .u64 t; cvta.to.shared.u64 t, %1; cvt.u32.u64 %0, t; }"
        : "=r"(a) : "l"(p));
    return a;
}
__device__ __forceinline__ void cp16(void* smem, const void* gmem) {
    asm volatile("cp.async.cg.shared.global [%0], [%1], 16;"
                 :: "r"(smem_u32(smem)), "l"(gmem) : "memory");
}
#define CP_COMMIT() asm volatile("cp.async.commit_group;" ::: "memory")
#define CP_WAIT0() asm volatile("cp.async.wait_group 0;" ::: "memory")

__device__ __forceinline__ void mma16816(float* d, const uint32_t* a,
                                         const uint32_t* b) {
    asm volatile(
        "mma.sync.aligned.m16n8k16.row.col.f32.bf16.bf16.f32 "
        "{%0,%1,%2,%3}, {%4,%5,%6,%7}, {%8,%9}, {%0,%1,%2,%3};"
        : "+f"(d[0]), "+f"(d[1]), "+f"(d[2]), "+f"(d[3])
        : "r"(a[0]), "r"(a[1]), "r"(a[2]), "r"(a[3]), "r"(b[0]), "r"(b[1]));
}

// ---------------- embedding: actT[b][s][c] (vectorized 8/thread) ------------
__global__ void embed_kernel(const int* __restrict__ ph,
                             const float* __restrict__ emb,
                             bf16* __restrict__ out) {
    int idx = blockIdx.x * blockDim.x + threadIdx.x;
    if (idx >= BB * SS * 64) return;
    int c8 = idx & 63;
    int s = (idx >> 6) & (SS - 1);
    int b = idx >> 14;
    const float* src = emb + (size_t)ph[b * SS + s] * 512 + c8 * 8;
    float4 f0 = *(const float4*)src;
    float4 f1 = *(const float4*)(src + 4);
    bf16 v[8];
    v[0] = __float2bfloat16(f0.x); v[1] = __float2bfloat16(f0.y);
    v[2] = __float2bfloat16(f0.z); v[3] = __float2bfloat16(f0.w);
    v[4] = __float2bfloat16(f1.x); v[5] = __float2bfloat16(f1.y);
    v[6] = __float2bfloat16(f1.z); v[7] = __float2bfloat16(f1.w);
    *(uint4*)(out + (size_t)idx * 8) = *(const uint4*)v;
}

// ------- fused weight repack (all layers, one launch) -----------------------
struct PrepArgs {
    const float* src[8];
    bf16* dst[8];
    int Cout[8], Cin[8], KT[8], CINP[8], total[8];
};
__global__ __launch_bounds__(256) void prep_all(PrepArgs pa) {
    int L = blockIdx.y;
    int idx8 = (blockIdx.x * 256 + threadIdx.x) * 8;
    if (idx8 >= pa.total[L]) return;
    const int CINP = pa.CINP[L], KTv = pa.KT[L], Cin = pa.Cin[L],
              Cout = pa.Cout[L];
    const int Ktot = CINP * KTv;
    int co = idx8 / Ktot, k = idx8 - co * Ktot;
    int t = k / CINP, ci = k - t * CINP;
    const float* w = pa.src[L];
    bf16 v[8];
#pragma unroll
    for (int j = 0; j < 8; j++) {
        float f = (co < Cout && ci + j < Cin)
                      ? w[((size_t)co * Cin + ci + j) * KTv + t]
                      : 0.f;
        v[j] = __float2bfloat16(f);
    }
    *(uint4*)(pa.dst[L] + idx8) = *(const uint4*)v;
}

// ------- mels transpose: melsT[b][t][ci] (bf16, ci padded to 96) ------------
__global__ __launch_bounds__(256) void melsT_kernel(const float* __restrict__ mels,
                                                    bf16* __restrict__ melsT) {
    __shared__ float tile[32][33];
    const int b = blockIdx.z;
    const int c0 = blockIdx.y * 32;
    const int t0 = blockIdx.x * 32;
    const int tx = threadIdx.x & 31, ty = threadIdx.x >> 5;
#pragma unroll
    for (int p = 0; p < 4; p++) {
        int c = ty + p * 8;
        tile[c][tx] = (c0 + c < 80 && t0 + tx < TT_TOT)
                          ? mels[((size_t)b * 80 + c0 + c) * TT_TOT + t0 + tx]
                          : 0.f;
    }
    __syncthreads();
#pragma unroll
    for (int p = 0; p < 4; p++) {
        int t = ty + p * 8;
        if (t0 + t < TT_TOT)
            melsT[((size_t)b * TT_TOT + t0 + t) * 96 + c0 + tx] =
                __float2bfloat16(tile[tx][t]);
    }
}

// ---------------- fused conv-as-GEMM (HMMA bf16) ----------------------------
// out[b][s][co] = act(bias[co] + sum_{t,ci} Aw[co][t*CINP+ci]*actT[b][s+t-P][ci])
// Block 128co x 128s, 8 warps 2x4, warp tile 64x32, K chunk CHUNK (dyn smem).
template <int KT, int CINP, int CHUNK, bool RELU>
__global__ __launch_bounds__(256) void gemm_conv(
    const bf16* __restrict__ Aw, const bf16* __restrict__ actT,
    const float* __restrict__ bias, bf16* __restrict__ outT,
    int Cout, int CS, int L) {
    constexpr int KTOT = KT * CINP;
    constexpr int NCH = KTOT / CHUNK;
    constexpr int PAD = KT / 2;
    constexpr int RP = CHUNK + 8;       // padded row (bf16)
    constexpr int UPR = CHUNK / 8;      // uint4 per row
    constexpr int KKN = CHUNK / 16;
    extern __shared__ __align__(16) bf16 dyn[];
    bf16* sA = dyn;                      // 2 bufs x 128 x RP
    bf16* sB = dyn + 2 * 128 * RP;

    const int tid = threadIdx.x;
    const int wid = tid >> 5, lane = tid & 31;
    const int wm = wid >> 2, wn = wid & 3;
    const int lr = lane >> 2, lc = (lane & 3) * 2;
    const int b = blockIdx.z, co0 = blockIdx.y * 128, s0 = blockIdx.x * 128;

    const bf16* gA = Aw + (size_t)co0 * KTOT;
    const bf16* actB = actT + (size_t)b * L * CINP;

    float acc[4][4][4];
#pragma unroll
    for (int i = 0; i < 4; i++)
#pragma unroll
        for (int j = 0; j < 4; j++)
#pragma unroll
            for (int v = 0; v < 4; v++) acc[i][j][v] = 0.f;

    auto load_chunk = [&](int buf, int ch) {
        const int k0 = ch * CHUNK;
        bf16* dA = sA + buf * 128 * RP;
        bf16* dB = sB + buf * 128 * RP;
#pragma unroll
        for (int n = 0; n < UPR / 2; n++) {
            int i = tid + n * 256;
            int row = i / UPR, u = i % UPR;
            cp16(dA + row * RP + u * 8, gA + (size_t)row * KTOT + k0 + u * 8);
        }
#pragma unroll
        for (int n = 0; n < UPR / 2; n++) {
            int i = tid + n * 256;
            int row = i / UPR, u = i % UPR;
            int k = k0 + u * 8;
            int t = k / CINP;
            int ci = k - t * CINP;
            int gs = s0 + row + t - PAD;
            const bf16* src = (gs >= 0 && gs < L)
                                  ? actB + (size_t)gs * CINP + ci
                                  : g_zero;
            cp16(dB + row * RP + u * 8, src);
        }
        CP_COMMIT();
    };

    load_chunk(0, 0);

    for (int ch = 0; ch < NCH; ch++) {
        CP_WAIT0();
        __syncthreads();
        if (ch + 1 < NCH) load_chunk((ch + 1) & 1, ch + 1);
        const bf16* Ab = sA + (ch & 1) * 128 * RP;
        const bf16* Bb = sB + (ch & 1) * 128 * RP;
#pragma unroll
        for (int kk = 0; kk < KKN; kk++) {
            uint32_t af[4][4];
#pragma unroll
            for (int im = 0; im < 4; im++) {
                const bf16* p = Ab + (wm * 64 + im * 16 + lr) * RP + kk * 16 + lc;
                af[im][0] = *(const uint32_t*)p;
                af[im][1] = *(const uint32_t*)(p + 8 * RP);
                af[im][2] = *(const uint32_t*)(p + 8);
                af[im][3] = *(const uint32_t*)(p + 8 * RP + 8);
            }
            uint32_t bfr[4][2];
#pragma unroll
            for (int in = 0; in < 4; in++) {
                const bf16* p = Bb + (wn * 32 + in * 8 + lr) * RP + kk * 16 + lc;
                bfr[in][0] = *(const uint32_t*)p;
                bfr[in][1] = *(const uint32_t*)(p + 8);
            }
#pragma unroll
            for (int im = 0; im < 4; im++)
#pragma unroll
                for (int in = 0; in < 4; in++)
                    mma16816(acc[im][in], af[im], bfr[in]);
        }
        __syncthreads();
    }

    // transposed epilogue: acc -> ep[s][co] (bf16, stride 72) -> stores
    bf16* ep = dyn;  // 128 x 72 bf16 (fits: 2*128*RP >= 128*72 for RP>=36)
#pragma unroll
    for (int c = 0; c < 2; c++) {
        if (wm == c) {
#pragma unroll
            for (int im = 0; im < 4; im++) {
                int co_loc = im * 16 + lr;
                int gco = co0 + c * 64 + co_loc;
                float b0v = (gco < Cout) ? bias[gco] : 0.f;
                float b1v = (gco + 8 < Cout) ? bias[gco + 8] : 0.f;
#pragma unroll
                for (int in = 0; in < 4; in++) {
                    int sl = wn * 32 + in * 8 + lc;
                    float* d = acc[im][in];
                    float v0 = d[0] + b0v, v1 = d[1] + b0v;
                    float v2 = d[2] + b1v, v3 = d[3] + b1v;
                    if (RELU) {
                        v0 = fmaxf(v0, 0.f); v1 = fmaxf(v1, 0.f);
                        v2 = fmaxf(v2, 0.f); v3 = fmaxf(v3, 0.f);
                    }
                    ep[sl * 72 + co_loc] = __float2bfloat16(v0);
                    ep[(sl + 1) * 72 + co_loc] = __float2bfloat16(v1);
                    ep[sl * 72 + co_loc + 8] = __float2bfloat16(v2);
                    ep[(sl + 1) * 72 + co_loc + 8] = __float2bfloat16(v3);
                }
            }
        }
        __syncthreads();
        int w = CS - (co0 + c * 64);
        if (w > 64) w = 64;
        if (w > 0) {
            int vpr = w >> 3;
            int tot = 128 * vpr;
            for (int idx = tid; idx < tot; idx += 256) {
                int s = idx / vpr, v = idx - s * vpr;
                if (s0 + s < L)
                    *(uint4*)(outT + ((size_t)b * L + s0 + s) * CS + co0 +
                              c * 64 + v * 8) = *(const uint4*)(ep + s * 72 + v * 8);
            }
        }
        __syncthreads();
    }
}

// ---------------- k squared-norm from kT [b][s][96] -------------------------
__global__ void k2_kernel(const bf16* __restrict__ kT, float* __restrict__ k2) {
    int idx = blockIdx.x * blockDim.x + threadIdx.x;
    if (idx >= BB * SS) return;
    const bf16* p = kT + (size_t)idx * 96;
    float sum = 0.f;
#pragma unroll
    for (int c = 0; c < 96; c++) {
        float v = __bfloat162float(p[c]);
        sum = fmaf(v, v, sum);
    }
    k2[idx] = sum;
}

// ---------------- fused attention: qk + log_softmax + prior + mask ----------
__global__ __launch_bounds__(256) void attn_kernel(
    const bf16* __restrict__ q2T, const bf16* __restrict__ kT,
    const float* __restrict__ k2, const float* __restrict__ prior,
    const int* __restrict__ mask, float* __restrict__ out) {
    constexpr float TEMP = 0.0005f;
    __shared__ float Ks[SS][17];
    __shared__ float Qs[16][16];
    __shared__ float redM[8][16], redS[8][16], lseS[16];

    const int b = blockIdx.y;
    const int t0 = blockIdx.x * 16;
    const int s = threadIdx.x;

    float acc[16];
#pragma unroll
    for (int tt = 0; tt < 16; tt++) acc[tt] = 0.f;

    for (int c0 = 0; c0 < 80; c0 += 16) {
        for (int i = threadIdx.x; i < SS * 16; i += 256) {
            int ss = i >> 4, cc = i & 15;
            Ks[ss][cc] =
                __bfloat162float(kT[((size_t)b * SS + ss) * 96 + c0 + cc]);
        }
        {
            int cc = threadIdx.x >> 4, tt = threadIdx.x & 15;
            int t = t0 + tt;
            Qs[cc][tt] = (t < TT_TOT)
                             ? __bfloat162float(
                                   q2T[((size_t)b * TT_TOT + t) * 96 + c0 + cc])
                             : 0.f;
        }
        __syncthreads();
#pragma unroll
        for (int cc = 0; cc < 16; cc++) {
            float kv = Ks[s][cc];
#pragma unroll
            for (int tt = 0; tt < 16; tt++)
                acc[tt] = fmaf(Qs[cc][tt], kv, acc[tt]);
        }
        __syncthreads();
    }

    const float k2v = k2[b * SS + s];
    const int lane = s & 31, wid = s >> 5;

    // logits (q2 row-constant cancels exactly under log_softmax)
#pragma unroll
    for (int tt = 0; tt < 16; tt++) acc[tt] = TEMP * (2.f * acc[tt] - k2v);

    // warp-level online (max, sum-exp) for all 16 rows; no block syncs
#pragma unroll
    for (int tt = 0; tt < 16; tt++) {
        float m = acc[tt], se = 1.f;
#pragma unroll
        for (int o = 16; o; o >>= 1) {
            float m2 = __shfl_xor_sync(~0u, m, o);
            float s2 = __shfl_xor_sync(~0u, se, o);
            float M = fmaxf(m, m2);
            se = se * __expf(m - M) + s2 * __expf(m2 - M);
            m = M;
        }
        if (lane == 0) { redM[wid][tt] = m; redS[wid][tt] = se; }
    }
    __syncthreads();
    // 16 designated threads combine the 8 warp partials
    if (lane < 2) {
        int tt = wid * 2 + lane;
        float M = redM[0][tt], SE = redS[0][tt];
#pragma unroll
        for (int i = 1; i < 8; i++) {
            float mi = redM[i][tt], si = redS[i][tt];
            float Mn = fmaxf(M, mi);
            SE = SE * __expf(M - Mn) + si * __expf(mi - Mn);
            M = Mn;
        }
        lseS[tt] = M + __logf(SE);
    }
    __syncthreads();

#pragma unroll
    for (int tt = 0; tt < 16; tt++) {
        int t = t0 + tt;
        if (t >= TT_TOT) break;  // uniform across block
        size_t oidx = ((size_t)(b * TT_TOT + t)) * SS + s;
        float val = acc[tt] - lseS[tt] + __logf(prior[oidx] + 1e-8f);
        out[oidx] = mask[oidx] ? val : -INFINITY;
    }
}

// ---------------- launch ----------------------------------------------------
extern "C" void kernel_launch(void* const* d_in, const int* in_sizes, int n_in,
                              void* d_out, int out_size) {
    const int* phonemes = (const int*)d_in[0];
    const float* mels = (const float*)d_in[1];
    const int* mask = (const int*)d_in[2];
    const float* prior = (const float*)d_in[3];
    const float* emb = (const float*)d_in[4];
    const float* kw[5] = {(const float*)d_in[5], (const float*)d_in[7],
                          (const float*)d_in[9], (const float*)d_in[11],
                          (const float*)d_in[13]};
    const float* kb[5] = {(const float*)d_in[6], (const float*)d_in[8],
                          (const float*)d_in[10], (const float*)d_in[12],
                          (const float*)d_in[14]};
    const float* qw[3] = {(const float*)d_in[15], (const float*)d_in[17],
                          (const float*)d_in[19]};
    const float* qb[3] = {(const float*)d_in[16], (const float*)d_in[18],
                          (const float*)d_in[20]};
    float* out = (float*)d_out;

    bf16 *pA0, *pA1, *pCT, *pKT, *pMT, *pQ0, *pQ1, *pQ2;
    bf16* pw[8];
    float* pk2;
    cudaGetSymbolAddress((void**)&pA0, g_actT0);
    cudaGetSymbolAddress((void**)&pA1, g_actT1);
    cudaGetSymbolAddress((void**)&pCT, g_cT);
    cudaGetSymbolAddress((void**)&pKT, g_kT);
    cudaGetSymbolAddress((void**)&pMT, g_melsT);
    cudaGetSymbolAddress((void**)&pQ0, g_q0T);
    cudaGetSymbolAddress((void**)&pQ1, g_q1T);
    cudaGetSymbolAddress((void**)&pQ2, g_q2T);
    cudaGetSymbolAddress((void**)&pw[0], g_w0);
    cudaGetSymbolAddress((void**)&pw[1], g_w1);
    cudaGetSymbolAddress((void**)&pw[2], g_w2);
    cudaGetSymbolAddress((void**)&pw[3], g_w3);
    cudaGetSymbolAddress((void**)&pw[4], g_w4);
    cudaGetSymbolAddress((void**)&pw[5], g_wq0);
    cudaGetSymbolAddress((void**)&pw[6], g_wq1);
    cudaGetSymbolAddress((void**)&pw[7], g_wq2);
    cudaGetSymbolAddress((void**)&pk2, g_k2v);

    // dynamic smem opt-in for CHUNK=64 instantiations (73728 B)
    const int SM64 = 1024 * 72, SM32 = 1024 * 40;
    cudaFuncSetAttribute(gemm_conv<5, 512, 64, true>,
                         cudaFuncAttributeMaxDynamicSharedMemorySize, SM64);
    cudaFuncSetAttribute(gemm_conv<3, 512, 64, true>,
                         cudaFuncAttributeMaxDynamicSharedMemorySize, SM64);
    cudaFuncSetAttribute(gemm_conv<1, 1024, 64, false>,
                         cudaFuncAttributeMaxDynamicSharedMemorySize, SM64);
    cudaFuncSetAttribute(gemm_conv<1, 192, 64, true>,
                         cudaFuncAttributeMaxDynamicSharedMemorySize, SM64);
    cudaFuncSetAttribute(gemm_conv<1, 128, 64, false>,
                         cudaFuncAttributeMaxDynamicSharedMemorySize, SM64);

    // embedding + mels transpose
    embed_kernel<<<(BB * SS * 64 + 255) / 256, 256>>>(phonemes, emb, pA0);
    melsT_kernel<<<dim3(47, 3, BB), 256>>>(mels, pMT);

    // all weight repacks in one launch
    PrepArgs pa;
    const int CoutA[8] = {512, 512, 512, 1024, 80, 160, 80, 80};
    const int CinA[8] = {512, 512, 512, 512, 1024, 80, 160, 80};
    const int KTA[8] = {5, 5, 5, 3, 1, 3, 1, 1};
    const int CINPA[8] = {512, 512, 512, 512, 1024, 96, 192, 128};
    const int RPAD[8] = {512, 512, 512, 1024, 128, 256, 128, 128};
    const float* srcs[8] = {kw[0], kw[1], kw[2], kw[3], kw[4],
                            qw[0], qw[1], qw[2]};
    for (int i = 0; i < 8; i++) {
        pa.src[i] = srcs[i];
        pa.dst[i] = pw[i];
        pa.Cout[i] = CoutA[i];
        pa.Cin[i] = CinA[i];
        pa.KT[i] = KTA[i];
        pa.CINP[i] = CINPA[i];
        pa.total[i] = RPAD[i] * KTA[i] * CINPA[i];
    }
    prep_all<<<dim3(768, 8), 256>>>(pa);

    // ---- key encoder ----
    gemm_conv<5, 512, 64, true><<<dim3(2, 4, BB), 256, SM64>>>(
        pw[0], pA0, kb[0], pA1, 512, 512, SS);
    gemm_conv<5, 512, 64, true><<<dim3(2, 4, BB), 256, SM64>>>(
        pw[1], pA1, kb[1], pA0, 512, 512, SS);
    gemm_conv<5, 512, 64, true><<<dim3(2, 4, BB), 256, SM64>>>(
        pw[2], pA0, kb[2], pA1, 512, 512, SS);
    gemm_conv<3, 512, 64, true><<<dim3(2, 8, BB), 256, SM64>>>(
        pw[3], pA1, kb[3], pCT, 1024, 1024, SS);
    gemm_conv<1, 1024, 64, false><<<dim3(2, 1, BB), 256, SM64>>>(
        pw[4], pCT, kb[4], pKT, 80, 96, SS);

    k2_kernel<<<(BB * SS + 255) / 256, 256>>>(pKT, pk2);

    // ---- query encoder ----
    gemm_conv<3, 96, 32, true><<<dim3(12, 2, BB), 256, SM32>>>(
        pw[5], pMT, qb[0], pQ0, 160, 192, TT_TOT);
    gemm_conv<1, 192, 64, true><<<dim3(12, 1, BB), 256, SM64>>>(
        pw[6], pQ0, qb[1], pQ1, 80, 128, TT_TOT);
    gemm_conv<1, 128, 64, false><<<dim3(12, 1, BB), 256, SM64>>>(
        pw[7], pQ1, qb[2], pQ2, 80, 96, TT_TOT);

    // fused attention + log_softmax + prior + mask
    attn_kernel<<<dim3((TT_TOT + 15) / 16, BB), 256>>>(pQ2, pKT, pk2, prior,
                                                       mask, out);
}

// round 8
// speedup vs baseline: 6.9436x; 1.0352x over previous
#include <cuda_runtime.h>
#include <cuda_bf16.h>
#include <math.h>
#include <stdint.h>

#define BB 32
#define TT_TOT 1500
#define SS 256

typedef __nv_bfloat16 bf16;

// ---------------- scratch buffers (device globals) --------------------------
__device__ __align__(16) bf16 g_actT0[BB * SS * 512];
__device__ __align__(16) bf16 g_actT1[BB * SS * 512];
__device__ __align__(16) bf16 g_cT[BB * SS * 1024];
__device__ __align__(16) bf16 g_kT[BB * SS * 96];
__device__ __align__(16) bf16 g_melsT[BB * TT_TOT * 96];
__device__ __align__(16) bf16 g_q0T[(size_t)BB * TT_TOT * 192];
__device__ __align__(16) bf16 g_q1T[(size_t)BB * TT_TOT * 128];
__device__ __align__(16) bf16 g_q2T[BB * TT_TOT * 96];
// per-layer repacked weights
__device__ __align__(16) bf16 g_w0[512 * 2560];
__device__ __align__(16) bf16 g_w1[512 * 2560];
__device__ __align__(16) bf16 g_w2[512 * 2560];
__device__ __align__(16) bf16 g_w3[1024 * 1536];
__device__ __align__(16) bf16 g_w4[128 * 1024];
__device__ __align__(16) bf16 g_wq0[256 * 288];
__device__ __align__(16) bf16 g_wq1[128 * 192];
__device__ __align__(16) bf16 g_wq2[128 * 128];
__device__ float g_k2v[BB * SS];
__device__ __align__(16) bf16 g_zero[8];  // zero page

// ---------------- helpers ----------------------------------------------------
__device__ __forceinline__ uint32_t smem_u32(const void* p) {
    uint32_t a;
    asm("{ .reg .u64 t; cvta.to.shared.u64 t, %1; cvt.u32.u64 %0, t; }"
        : "=r"(a) : "l"(p));
    return a;
}
__device__ __forceinline__ void cp16(void* smem, const void* gmem) {
    asm volatile("cp.async.cg.shared.global [%0], [%1], 16;"
                 :: "r"(smem_u32(smem)), "l"(gmem) : "memory");
}
#define CP_COMMIT() asm volatile("cp.async.commit_group;" ::: "memory")
#define CP_WAIT0() asm volatile("cp.async.wait_group 0;" ::: "memory")

__device__ __forceinline__ void mma16816(float* d, const uint32_t* a,
                                         const uint32_t* b) {
    asm volatile(
        "mma.sync.aligned.m16n8k16.row.col.f32.bf16.bf16.f32 "
        "{%0,%1,%2,%3}, {%4,%5,%6,%7}, {%8,%9}, {%0,%1,%2,%3};"
        : "+f"(d[0]), "+f"(d[1]), "+f"(d[2]), "+f"(d[3])
        : "r"(a[0]), "r"(a[1]), "r"(a[2]), "r"(a[3]), "r"(b[0]), "r"(b[1]));
}
__device__ __forceinline__ void ldsm4(uint32_t& r0, uint32_t& r1, uint32_t& r2,
                                      uint32_t& r3, uint32_t addr) {
    asm volatile("ldmatrix.sync.aligned.m8n8.x4.shared.b16 {%0,%1,%2,%3}, [%4];"
                 : "=r"(r0), "=r"(r1), "=r"(r2), "=r"(r3) : "r"(addr));
}

// ---------------- embedding: actT[b][s][c] (vectorized 8/thread) ------------
__global__ void embed_kernel(const int* __restrict__ ph,
                             const float* __restrict__ emb,
                             bf16* __restrict__ out) {
    int idx = blockIdx.x * blockDim.x + threadIdx.x;
    if (idx >= BB * SS * 64) return;
    int c8 = idx & 63;
    int s = (idx >> 6) & (SS - 1);
    int b = idx >> 14;
    const float* src = emb + (size_t)ph[b * SS + s] * 512 + c8 * 8;
    float4 f0 = *(const float4*)src;
    float4 f1 = *(const float4*)(src + 4);
    bf16 v[8];
    v[0] = __float2bfloat16(f0.x); v[1] = __float2bfloat16(f0.y);
    v[2] = __float2bfloat16(f0.z); v[3] = __float2bfloat16(f0.w);
    v[4] = __float2bfloat16(f1.x); v[5] = __float2bfloat16(f1.y);
    v[6] = __float2bfloat16(f1.z); v[7] = __float2bfloat16(f1.w);
    *(uint4*)(out + (size_t)idx * 8) = *(const uint4*)v;
}

// ------- fused weight repack (all layers, one launch) -----------------------
struct PrepArgs {
    const float* src[8];
    bf16* dst[8];
    int Cout[8], Cin[8], KT[8], CINP[8], total[8];
};
__global__ __launch_bounds__(256) void prep_all(PrepArgs pa) {
    int L = blockIdx.y;
    int idx8 = (blockIdx.x * 256 + threadIdx.x) * 8;
    if (idx8 >= pa.total[L]) return;
    const int CINP = pa.CINP[L], KTv = pa.KT[L], Cin = pa.Cin[L],
              Cout = pa.Cout[L];
    const int Ktot = CINP * KTv;
    int co = idx8 / Ktot, k = idx8 - co * Ktot;
    int t = k / CINP, ci = k - t * CINP;
    const float* w = pa.src[L];
    bf16 v[8];
#pragma unroll
    for (int j = 0; j < 8; j++) {
        float f = (co < Cout && ci + j < Cin)
                      ? w[((size_t)co * Cin + ci + j) * KTv + t]
                      : 0.f;
        v[j] = __float2bfloat16(f);
    }
    *(uint4*)(pa.dst[L] + idx8) = *(const uint4*)v;
}

// ------- mels transpose: melsT[b][t][ci] (bf16, ci padded to 96) ------------
__global__ __launch_bounds__(256) void melsT_kernel(const float* __restrict__ mels,
                                                    bf16* __restrict__ melsT) {
    __shared__ float tile[32][33];
    const int b = blockIdx.z;
    const int c0 = blockIdx.y * 32;
    const int t0 = blockIdx.x * 32;
    const int tx = threadIdx.x & 31, ty = threadIdx.x >> 5;
#pragma unroll
    for (int p = 0; p < 4; p++) {
        int c = ty + p * 8;
        tile[c][tx] = (c0 + c < 80 && t0 + tx < TT_TOT)
                          ? mels[((size_t)b * 80 + c0 + c) * TT_TOT + t0 + tx]
                          : 0.f;
    }
    __syncthreads();
#pragma unroll
    for (int p = 0; p < 4; p++) {
        int t = ty + p * 8;
        if (t0 + t < TT_TOT)
            melsT[((size_t)b * TT_TOT + t0 + t) * 96 + c0 + tx] =
                __float2bfloat16(tile[tx][t]);
    }
}

// ---------------- fused conv-as-GEMM (HMMA bf16 + ldmatrix) -----------------
// out[b][s][co] = act(bias[co] + sum_{t,ci} Aw[co][t*CINP+ci]*actT[b][s+t-P][ci])
// Block 128co x 128s, 8 warps 2x4, warp tile 64x32, K chunk CHUNK (dyn smem).
template <int KT, int CINP, int CHUNK, bool RELU>
__global__ __launch_bounds__(256) void gemm_conv(
    const bf16* __restrict__ Aw, const bf16* __restrict__ actT,
    const float* __restrict__ bias, bf16* __restrict__ outT,
    int Cout, int CS, int L) {
    constexpr int KTOT = KT * CINP;
    constexpr int NCH = KTOT / CHUNK;
    constexpr int PAD = KT / 2;
    constexpr int RP = CHUNK + 8;       // padded row (bf16); row stride 16B-mult
    constexpr int UPR = CHUNK / 8;      // uint4 per row
    constexpr int KKN = CHUNK / 16;
    extern __shared__ __align__(16) bf16 dyn[];
    bf16* sA = dyn;                      // 2 bufs x 128 x RP
    bf16* sB = dyn + 2 * 128 * RP;

    const int tid = threadIdx.x;
    const int wid = tid >> 5, lane = tid & 31;
    const int wm = wid >> 2, wn = wid & 3;
    const int lr = lane >> 2, lc = (lane & 3) * 2;
    const int b = blockIdx.z, co0 = blockIdx.y * 128, s0 = blockIdx.x * 128;

    const bf16* gA = Aw + (size_t)co0 * KTOT;
    const bf16* actB = actT + (size_t)b * L * CINP;

    // ldmatrix lane-address components (elements)
    const int lmA_off = ((lane & 7) + ((lane >> 3) & 1) * 8) * RP +
                        (lane >> 4) * 8;
    const int lmB_off = ((lane & 7) + ((lane >> 4) & 1) * 8) * RP +
                        ((lane >> 3) & 1) * 8;
    const uint32_t aLm0 = smem_u32(sA + (wm * 64) * RP + lmA_off);
    const uint32_t bLm0 = smem_u32(sB + (wn * 32) * RP + lmB_off);
    constexpr uint32_t BUFB = 128 * RP * 2;  // buffer stride in bytes

    float acc[4][4][4];
#pragma unroll
    for (int i = 0; i < 4; i++)
#pragma unroll
        for (int j = 0; j < 4; j++)
#pragma unroll
            for (int v = 0; v < 4; v++) acc[i][j][v] = 0.f;

    auto load_chunk = [&](int buf, int ch) {
        const int k0 = ch * CHUNK;
        bf16* dA = sA + buf * 128 * RP;
        bf16* dB = sB + buf * 128 * RP;
#pragma unroll
        for (int n = 0; n < UPR / 2; n++) {
            int i = tid + n * 256;
            int row = i / UPR, u = i % UPR;
            cp16(dA + row * RP + u * 8, gA + (size_t)row * KTOT + k0 + u * 8);
        }
#pragma unroll
        for (int n = 0; n < UPR / 2; n++) {
            int i = tid + n * 256;
            int row = i / UPR, u = i % UPR;
            int k = k0 + u * 8;
            int t = k / CINP;
            int ci = k - t * CINP;
            int gs = s0 + row + t - PAD;
            const bf16* src = (gs >= 0 && gs < L)
                                  ? actB + (size_t)gs * CINP + ci
                                  : g_zero;
            cp16(dB + row * RP + u * 8, src);
        }
        CP_COMMIT();
    };

    load_chunk(0, 0);

    for (int ch = 0; ch < NCH; ch++) {
        CP_WAIT0();
        __syncthreads();
        if (ch + 1 < NCH) load_chunk((ch + 1) & 1, ch + 1);
        const uint32_t aB = aLm0 + (ch & 1) * BUFB;
        const uint32_t bB = bLm0 + (ch & 1) * BUFB;
#pragma unroll
        for (int kk = 0; kk < KKN; kk++) {
            uint32_t af[4][4];
#pragma unroll
            for (int im = 0; im < 4; im++)
                ldsm4(af[im][0], af[im][1], af[im][2], af[im][3],
                      aB + (im * 16 * RP + kk * 16) * 2);
            uint32_t bfr[4][2];
#pragma unroll
            for (int h = 0; h < 2; h++)
                ldsm4(bfr[2 * h][0], bfr[2 * h][1], bfr[2 * h + 1][0],
                      bfr[2 * h + 1][1], bB + (h * 16 * RP + kk * 16) * 2);
#pragma unroll
            for (int im = 0; im < 4; im++)
#pragma unroll
                for (int in = 0; in < 4; in++)
                    mma16816(acc[im][in], af[im], bfr[in]);
        }
        __syncthreads();
    }

    // transposed epilogue: acc -> ep[s][co] (bf16, stride 72) -> stores
    bf16* ep = dyn;  // 128 x 72 bf16
#pragma unroll
    for (int c = 0; c < 2; c++) {
        if (wm == c) {
#pragma unroll
            for (int im = 0; im < 4; im++) {
                int co_loc = im * 16 + lr;
                int gco = co0 + c * 64 + co_loc;
                float b0v = (gco < Cout) ? bias[gco] : 0.f;
                float b1v = (gco + 8 < Cout) ? bias[gco + 8] : 0.f;
#pragma unroll
                for (int in = 0; in < 4; in++) {
                    int sl = wn * 32 + in * 8 + lc;
                    float* d = acc[im][in];
                    float v0 = d[0] + b0v, v1 = d[1] + b0v;
                    float v2 = d[2] + b1v, v3 = d[3] + b1v;
                    if (RELU) {
                        v0 = fmaxf(v0, 0.f); v1 = fmaxf(v1, 0.f);
                        v2 = fmaxf(v2, 0.f); v3 = fmaxf(v3, 0.f);
                    }
                    ep[sl * 72 + co_loc] = __float2bfloat16(v0);
                    ep[(sl + 1) * 72 + co_loc] = __float2bfloat16(v1);
                    ep[sl * 72 + co_loc + 8] = __float2bfloat16(v2);
                    ep[(sl + 1) * 72 + co_loc + 8] = __float2bfloat16(v3);
                }
            }
        }
        __syncthreads();
        int w = CS - (co0 + c * 64);
        if (w > 64) w = 64;
        if (w > 0) {
            int vpr = w >> 3;
            int tot = 128 * vpr;
            for (int idx = tid; idx < tot; idx += 256) {
                int s = idx / vpr, v = idx - s * vpr;
                if (s0 + s < L)
                    *(uint4*)(outT + ((size_t)b * L + s0 + s) * CS + co0 +
                              c * 64 + v * 8) = *(const uint4*)(ep + s * 72 + v * 8);
            }
        }
        __syncthreads();
    }
}

// ---------------- k squared-norm from kT [b][s][96] -------------------------
__global__ void k2_kernel(const bf16* __restrict__ kT, float* __restrict__ k2) {
    int idx = blockIdx.x * blockDim.x + threadIdx.x;
    if (idx >= BB * SS) return;
    const bf16* p = kT + (size_t)idx * 96;
    float sum = 0.f;
#pragma unroll
    for (int c = 0; c < 96; c++) {
        float v = __bfloat162float(p[c]);
        sum = fmaf(v, v, sum);
    }
    k2[idx] = sum;
}

// ---------------- fused attention: qk + log_softmax + prior + mask ----------
// 32 t-rows per block, one thread per s.
__global__ __launch_bounds__(256) void attn_kernel(
    const bf16* __restrict__ q2T, const bf16* __restrict__ kT,
    const float* __restrict__ k2, const float* __restrict__ prior,
    const int* __restrict__ mask, float* __restrict__ out) {
    constexpr float TEMP = 0.0005f;
    constexpr int TTILE = 32;
    __shared__ float Ks[SS][17];
    __shared__ float Qs[16][TTILE];
    __shared__ float redM[8][TTILE], redS[8][TTILE], lseS[TTILE];

    const int b = blockIdx.y;
    const int t0 = blockIdx.x * TTILE;
    const int s = threadIdx.x;

    float acc[TTILE];
#pragma unroll
    for (int tt = 0; tt < TTILE; tt++) acc[tt] = 0.f;

    for (int c0 = 0; c0 < 80; c0 += 16) {
        for (int i = threadIdx.x; i < SS * 16; i += 256) {
            int ss = i >> 4, cc = i & 15;
            Ks[ss][cc] =
                __bfloat162float(kT[((size_t)b * SS + ss) * 96 + c0 + cc]);
        }
        for (int i = threadIdx.x; i < 16 * TTILE; i += 256) {
            int cc = i >> 5, tt = i & (TTILE - 1);
            int t = t0 + tt;
            Qs[cc][tt] = (t < TT_TOT)
                             ? __bfloat162float(
                                   q2T[((size_t)b * TT_TOT + t) * 96 + c0 + cc])
                             : 0.f;
        }
        __syncthreads();
#pragma unroll
        for (int cc = 0; cc < 16; cc++) {
            float kv = Ks[s][cc];
#pragma unroll
            for (int tt = 0; tt < TTILE; tt++)
                acc[tt] = fmaf(Qs[cc][tt], kv, acc[tt]);
        }
        __syncthreads();
    }

    const float k2v = k2[b * SS + s];
    const int lane = s & 31, wid = s >> 5;

#pragma unroll
    for (int tt = 0; tt < TTILE; tt++) acc[tt] = TEMP * (2.f * acc[tt] - k2v);

    // warp-level online (max, sum-exp) for all rows
#pragma unroll
    for (int tt = 0; tt < TTILE; tt++) {
        float m = acc[tt], se = 1.f;
#pragma unroll
        for (int o = 16; o; o >>= 1) {
            float m2 = __shfl_xor_sync(~0u, m, o);
            float s2 = __shfl_xor_sync(~0u, se, o);
            float M = fmaxf(m, m2);
            se = se * __expf(m - M) + s2 * __expf(m2 - M);
            m = M;
        }
        if (lane == 0) { redM[wid][tt] = m; redS[wid][tt] = se; }
    }
    __syncthreads();
    // 32 designated threads combine the 8 warp partials
    if (lane < 4) {
        int tt = wid * 4 + lane;
        float M = redM[0][tt], SE = redS[0][tt];
#pragma unroll
        for (int i = 1; i < 8; i++) {
            float mi = redM[i][tt], si = redS[i][tt];
            float Mn = fmaxf(M, mi);
            SE = SE * __expf(M - Mn) + si * __expf(mi - Mn);
            M = Mn;
        }
        lseS[tt] = M + __logf(SE);
    }
    __syncthreads();

#pragma unroll
    for (int tt = 0; tt < TTILE; tt++) {
        int t = t0 + tt;
        if (t >= TT_TOT) break;  // uniform across block
        size_t oidx = ((size_t)(b * TT_TOT + t)) * SS + s;
        float val = acc[tt] - lseS[tt] + __logf(prior[oidx] + 1e-8f);
        out[oidx] = mask[oidx] ? val : -INFINITY;
    }
}

// ---------------- launch ----------------------------------------------------
extern "C" void kernel_launch(void* const* d_in, const int* in_sizes, int n_in,
                              void* d_out, int out_size) {
    const int* phonemes = (const int*)d_in[0];
    const float* mels = (const float*)d_in[1];
    const int* mask = (const int*)d_in[2];
    const float* prior = (const float*)d_in[3];
    const float* emb = (const float*)d_in[4];
    const float* kw[5] = {(const float*)d_in[5], (const float*)d_in[7],
                          (const float*)d_in[9], (const float*)d_in[11],
                          (const float*)d_in[13]};
    const float* kb[5] = {(const float*)d_in[6], (const float*)d_in[8],
                          (const float*)d_in[10], (const float*)d_in[12],
                          (const float*)d_in[14]};
    const float* qw[3] = {(const float*)d_in[15], (const float*)d_in[17],
                          (const float*)d_in[19]};
    const float* qb[3] = {(const float*)d_in[16], (const float*)d_in[18],
                          (const float*)d_in[20]};
    float* out = (float*)d_out;

    bf16 *pA0, *pA1, *pCT, *pKT, *pMT, *pQ0, *pQ1, *pQ2;
    bf16* pw[8];
    float* pk2;
    cudaGetSymbolAddress((void**)&pA0, g_actT0);
    cudaGetSymbolAddress((void**)&pA1, g_actT1);
    cudaGetSymbolAddress((void**)&pCT, g_cT);
    cudaGetSymbolAddress((void**)&pKT, g_kT);
    cudaGetSymbolAddress((void**)&pMT, g_melsT);
    cudaGetSymbolAddress((void**)&pQ0, g_q0T);
    cudaGetSymbolAddress((void**)&pQ1, g_q1T);
    cudaGetSymbolAddress((void**)&pQ2, g_q2T);
    cudaGetSymbolAddress((void**)&pw[0], g_w0);
    cudaGetSymbolAddress((void**)&pw[1], g_w1);
    cudaGetSymbolAddress((void**)&pw[2], g_w2);
    cudaGetSymbolAddress((void**)&pw[3], g_w3);
    cudaGetSymbolAddress((void**)&pw[4], g_w4);
    cudaGetSymbolAddress((void**)&pw[5], g_wq0);
    cudaGetSymbolAddress((void**)&pw[6], g_wq1);
    cudaGetSymbolAddress((void**)&pw[7], g_wq2);
    cudaGetSymbolAddress((void**)&pk2, g_k2v);

    // dynamic smem opt-in for CHUNK=64 instantiations (73728 B)
    const int SM64 = 1024 * 72, SM32 = 1024 * 40;
    cudaFuncSetAttribute(gemm_conv<5, 512, 64, true>,
                         cudaFuncAttributeMaxDynamicSharedMemorySize, SM64);
    cudaFuncSetAttribute(gemm_conv<3, 512, 64, true>,
                         cudaFuncAttributeMaxDynamicSharedMemorySize, SM64);
    cudaFuncSetAttribute(gemm_conv<1, 1024, 64, false>,
                         cudaFuncAttributeMaxDynamicSharedMemorySize, SM64);
    cudaFuncSetAttribute(gemm_conv<1, 192, 64, true>,
                         cudaFuncAttributeMaxDynamicSharedMemorySize, SM64);
    cudaFuncSetAttribute(gemm_conv<1, 128, 64, false>,
                         cudaFuncAttributeMaxDynamicSharedMemorySize, SM64);

    // embedding + mels transpose
    embed_kernel<<<(BB * SS * 64 + 255) / 256, 256>>>(phonemes, emb, pA0);
    melsT_kernel<<<dim3(47, 3, BB), 256>>>(mels, pMT);

    // all weight repacks in one launch
    PrepArgs pa;
    const int CoutA[8] = {512, 512, 512, 1024, 80, 160, 80, 80};
    const int CinA[8] = {512, 512, 512, 512, 1024, 80, 160, 80};
    const int KTA[8] = {5, 5, 5, 3, 1, 3, 1, 1};
    const int CINPA[8] = {512, 512, 512, 512, 1024, 96, 192, 128};
    const int RPAD[8] = {512, 512, 512, 1024, 128, 256, 128, 128};
    const float* srcs[8] = {kw[0], kw[1], kw[2], kw[3], kw[4],
                            qw[0], qw[1], qw[2]};
    for (int i = 0; i < 8; i++) {
        pa.src[i] = srcs[i];
        pa.dst[i] = pw[i];
        pa.Cout[i] = CoutA[i];
        pa.Cin[i] = CinA[i];
        pa.KT[i] = KTA[i];
        pa.CINP[i] = CINPA[i];
        pa.total[i] = RPAD[i] * KTA[i] * CINPA[i];
    }
    prep_all<<<dim3(768, 8), 256>>>(pa);

    // ---- key encoder ----
    gemm_conv<5, 512, 64, true><<<dim3(2, 4, BB), 256, SM64>>>(
        pw[0], pA0, kb[0], pA1, 512, 512, SS);
    gemm_conv<5, 512, 64, true><<<dim3(2, 4, BB), 256, SM64>>>(
        pw[1], pA1, kb[1], pA0, 512, 512, SS);
    gemm_conv<5, 512, 64, true><<<dim3(2, 4, BB), 256, SM64>>>(
        pw[2], pA0, kb[2], pA1, 512, 512, SS);
    gemm_conv<3, 512, 64, true><<<dim3(2, 8, BB), 256, SM64>>>(
        pw[3], pA1, kb[3], pCT, 1024, 1024, SS);
    gemm_conv<1, 1024, 64, false><<<dim3(2, 1, BB), 256, SM64>>>(
        pw[4], pCT, kb[4], pKT, 80, 96, SS);

    k2_kernel<<<(BB * SS + 255) / 256, 256>>>(pKT, pk2);

    // ---- query encoder ----
    gemm_conv<3, 96, 32, true><<<dim3(12, 2, BB), 256, SM32>>>(
        pw[5], pMT, qb[0], pQ0, 160, 192, TT_TOT);
    gemm_conv<1, 192, 64, true><<<dim3(12, 1, BB), 256, SM64>>>(
        pw[6], pQ0, qb[1], pQ1, 80, 128, TT_TOT);
    gemm_conv<1, 128, 64, false><<<dim3(12, 1, BB), 256, SM64>>>(
        pw[7], pQ1, qb[2], pQ2, 80, 96, TT_TOT);

    // fused attention + log_softmax + prior + mask
    attn_kernel<<<dim3((TT_TOT + 31) / 32, BB), 256>>>(pQ2, pKT, pk2, prior,
                                                       mask, out);
}

// round 9
// speedup vs baseline: 8.6499x; 1.2458x over previous
#include <cuda_runtime.h>
#include <cuda_bf16.h>
#include <math.h>
#include <stdint.h>

#define BB 32
#define TT_TOT 1500
#define SS 256

typedef __nv_bfloat16 bf16;

// ---------------- scratch buffers (device globals) --------------------------
__device__ __align__(16) bf16 g_actT0[BB * SS * 512];
__device__ __align__(16) bf16 g_actT1[BB * SS * 512];
__device__ __align__(16) bf16 g_cT[BB * SS * 1024];
__device__ __align__(16) bf16 g_kT[BB * SS * 96];
__device__ __align__(16) bf16 g_melsT[BB * TT_TOT * 96];
__device__ __align__(16) bf16 g_q0T[(size_t)BB * TT_TOT * 192];
__device__ __align__(16) bf16 g_q1T[(size_t)BB * TT_TOT * 128];
__device__ __align__(16) bf16 g_q2T[BB * TT_TOT * 96];
// per-layer repacked weights
__device__ __align__(16) bf16 g_w0[512 * 2560];
__device__ __align__(16) bf16 g_w1[512 * 2560];
__device__ __align__(16) bf16 g_w2[512 * 2560];
__device__ __align__(16) bf16 g_w3[1024 * 1536];
__device__ __align__(16) bf16 g_w4[128 * 1024];
__device__ __align__(16) bf16 g_wq0[256 * 288];
__device__ __align__(16) bf16 g_wq1[128 * 192];
__device__ __align__(16) bf16 g_wq2[128 * 128];
__device__ float g_k2v[BB * SS];
__device__ __align__(16) bf16 g_zero[8];  // zero page

// ---------------- helpers ----------------------------------------------------
__device__ __forceinline__ uint32_t smem_u32(const void* p) {
    uint32_t a;
    asm("{ .reg .u64 t; cvta.to.shared.u64 t, %1; cvt.u32.u64 %0, t; }"
        : "=r"(a) : "l"(p));
    return a;
}
__device__ __forceinline__ void cp16(void* smem, const void* gmem) {
    asm volatile("cp.async.cg.shared.global [%0], [%1], 16;"
                 :: "r"(smem_u32(smem)), "l"(gmem) : "memory");
}
#define CP_COMMIT() asm volatile("cp.async.commit_group;" ::: "memory")
#define CP_WAIT0() asm volatile("cp.async.wait_group 0;" ::: "memory")
#define CP_WAIT1() asm volatile("cp.async.wait_group 1;" ::: "memory")

__device__ __forceinline__ void mma16816(float* d, const uint32_t* a,
                                         const uint32_t* b) {
    asm volatile(
        "mma.sync.aligned.m16n8k16.row.col.f32.bf16.bf16.f32 "
        "{%0,%1,%2,%3}, {%4,%5,%6,%7}, {%8,%9}, {%0,%1,%2,%3};"
        : "+f"(d[0]), "+f"(d[1]), "+f"(d[2]), "+f"(d[3])
        : "r"(a[0]), "r"(a[1]), "r"(a[2]), "r"(a[3]), "r"(b[0]), "r"(b[1]));
}
__device__ __forceinline__ void ldsm4(uint32_t& r0, uint32_t& r1, uint32_t& r2,
                                      uint32_t& r3, uint32_t addr) {
    asm volatile("ldmatrix.sync.aligned.m8n8.x4.shared.b16 {%0,%1,%2,%3}, [%4];"
                 : "=r"(r0), "=r"(r1), "=r"(r2), "=r"(r3) : "r"(addr));
}

// ---------------- embedding: actT[b][s][c] (vectorized 8/thread) ------------
__global__ void embed_kernel(const int* __restrict__ ph,
                             const float* __restrict__ emb,
                             bf16* __restrict__ out) {
    int idx = blockIdx.x * blockDim.x + threadIdx.x;
    if (idx >= BB * SS * 64) return;
    int c8 = idx & 63;
    int s = (idx >> 6) & (SS - 1);
    int b = idx >> 14;
    const float* src = emb + (size_t)ph[b * SS + s] * 512 + c8 * 8;
    float4 f0 = *(const float4*)src;
    float4 f1 = *(const float4*)(src + 4);
    bf16 v[8];
    v[0] = __float2bfloat16(f0.x); v[1] = __float2bfloat16(f0.y);
    v[2] = __float2bfloat16(f0.z); v[3] = __float2bfloat16(f0.w);
    v[4] = __float2bfloat16(f1.x); v[5] = __float2bfloat16(f1.y);
    v[6] = __float2bfloat16(f1.z); v[7] = __float2bfloat16(f1.w);
    *(uint4*)(out + (size_t)idx * 8) = *(const uint4*)v;
}

// ------- fused weight repack (all layers, one launch) -----------------------
struct PrepArgs {
    const float* src[8];
    bf16* dst[8];
    int Cout[8], Cin[8], KT[8], CINP[8], total[8];
};
__global__ __launch_bounds__(256) void prep_all(PrepArgs pa) {
    int L = blockIdx.y;
    int idx8 = (blockIdx.x * 256 + threadIdx.x) * 8;
    if (idx8 >= pa.total[L]) return;
    const int CINP = pa.CINP[L], KTv = pa.KT[L], Cin = pa.Cin[L],
              Cout = pa.Cout[L];
    const int Ktot = CINP * KTv;
    int co = idx8 / Ktot, k = idx8 - co * Ktot;
    int t = k / CINP, ci = k - t * CINP;
    const float* w = pa.src[L];
    bf16 v[8];
#pragma unroll
    for (int j = 0; j < 8; j++) {
        float f = (co < Cout && ci + j < Cin)
                      ? w[((size_t)co * Cin + ci + j) * KTv + t]
                      : 0.f;
        v[j] = __float2bfloat16(f);
    }
    *(uint4*)(pa.dst[L] + idx8) = *(const uint4*)v;
}

// ------- mels transpose: melsT[b][t][ci] (bf16, ci padded to 96) ------------
__global__ __launch_bounds__(256) void melsT_kernel(const float* __restrict__ mels,
                                                    bf16* __restrict__ melsT) {
    __shared__ float tile[32][33];
    const int b = blockIdx.z;
    const int c0 = blockIdx.y * 32;
    const int t0 = blockIdx.x * 32;
    const int tx = threadIdx.x & 31, ty = threadIdx.x >> 5;
#pragma unroll
    for (int p = 0; p < 4; p++) {
        int c = ty + p * 8;
        tile[c][tx] = (c0 + c < 80 && t0 + tx < TT_TOT)
                          ? mels[((size_t)b * 80 + c0 + c) * TT_TOT + t0 + tx]
                          : 0.f;
    }
    __syncthreads();
#pragma unroll
    for (int p = 0; p < 4; p++) {
        int t = ty + p * 8;
        if (t0 + t < TT_TOT)
            melsT[((size_t)b * TT_TOT + t0 + t) * 96 + c0 + tx] =
                __float2bfloat16(tile[tx][t]);
    }
}

// ---------------- fused conv-as-GEMM (HMMA bf16 + ldmatrix, 3-stage) --------
// out[b][s][co] = act(bias[co] + sum_{t,ci} Aw[co][t*CINP+ci]*actT[b][s+t-P][ci])
// Block 128co x 128s, 8 warps 2x4, warp tile 64x32, K chunk CHUNK, 3 stages.
template <int KT, int CINP, int CHUNK, bool RELU>
__global__ __launch_bounds__(256, 2) void gemm_conv(
    const bf16* __restrict__ Aw, const bf16* __restrict__ actT,
    const float* __restrict__ bias, bf16* __restrict__ outT,
    int Cout, int CS, int L) {
    constexpr int KTOT = KT * CINP;
    constexpr int NCH = KTOT / CHUNK;
    constexpr int PAD = KT / 2;
    constexpr int RP = CHUNK + 8;
    constexpr int UPR = CHUNK / 8;
    constexpr int KKN = CHUNK / 16;
    constexpr int STG = 2 * 128 * RP;   // elems per stage (A then B)
    extern __shared__ __align__(16) bf16 dyn[];

    const int tid = threadIdx.x;
    const int wid = tid >> 5, lane = tid & 31;
    const int wm = wid >> 2, wn = wid & 3;
    const int lr = lane >> 2, lc = (lane & 3) * 2;
    const int b = blockIdx.z, co0 = blockIdx.y * 128, s0 = blockIdx.x * 128;

    const bf16* gA = Aw + (size_t)co0 * KTOT;
    const bf16* actB = actT + (size_t)b * L * CINP;

    const int lmA_off = ((lane & 7) + ((lane >> 3) & 1) * 8) * RP +
                        (lane >> 4) * 8;
    const int lmB_off = ((lane & 7) + ((lane >> 4) & 1) * 8) * RP +
                        ((lane >> 3) & 1) * 8;
    const uint32_t aLm0 = smem_u32(dyn + (wm * 64) * RP + lmA_off);
    const uint32_t bLm0 = smem_u32(dyn + 128 * RP + (wn * 32) * RP + lmB_off);
    constexpr uint32_t STGB = STG * 2;  // stage stride bytes

    float acc[4][4][4];
#pragma unroll
    for (int i = 0; i < 4; i++)
#pragma unroll
        for (int j = 0; j < 4; j++)
#pragma unroll
            for (int v = 0; v < 4; v++) acc[i][j][v] = 0.f;

    auto load_chunk = [&](int stg, int ch) {
        const int k0 = ch * CHUNK;
        bf16* dA = dyn + stg * STG;
        bf16* dB = dA + 128 * RP;
#pragma unroll
        for (int n = 0; n < UPR / 2; n++) {
            int i = tid + n * 256;
            int row = i / UPR, u = i % UPR;
            cp16(dA + row * RP + u * 8, gA + (size_t)row * KTOT + k0 + u * 8);
        }
#pragma unroll
        for (int n = 0; n < UPR / 2; n++) {
            int i = tid + n * 256;
            int row = i / UPR, u = i % UPR;
            int k = k0 + u * 8;
            int t = k / CINP;
            int ci = k - t * CINP;
            int gs = s0 + row + t - PAD;
            const bf16* src = (gs >= 0 && gs < L)
                                  ? actB + (size_t)gs * CINP + ci
                                  : g_zero;
            cp16(dB + row * RP + u * 8, src);
        }
        CP_COMMIT();
    };

    load_chunk(0, 0);
    load_chunk(1, 1);

    int st = 0, st2 = 2;
    for (int ch = 0; ch < NCH; ch++) {
        if (ch + 1 < NCH) { CP_WAIT1(); } else { CP_WAIT0(); }
        __syncthreads();
        if (ch + 2 < NCH) load_chunk(st2, ch + 2);
        const uint32_t aB = aLm0 + st * STGB;
        const uint32_t bB = bLm0 + st * STGB;
#pragma unroll
        for (int kk = 0; kk < KKN; kk++) {
            uint32_t af[4][4];
#pragma unroll
            for (int im = 0; im < 4; im++)
                ldsm4(af[im][0], af[im][1], af[im][2], af[im][3],
                      aB + (im * 16 * RP + kk * 16) * 2);
            uint32_t bfr[4][2];
#pragma unroll
            for (int h = 0; h < 2; h++)
                ldsm4(bfr[2 * h][0], bfr[2 * h][1], bfr[2 * h + 1][0],
                      bfr[2 * h + 1][1], bB + (h * 16 * RP + kk * 16) * 2);
#pragma unroll
            for (int im = 0; im < 4; im++)
#pragma unroll
                for (int in = 0; in < 4; in++)
                    mma16816(acc[im][in], af[im], bfr[in]);
        }
        st = (st == 2) ? 0 : st + 1;
        st2 = (st2 == 2) ? 0 : st2 + 1;
    }
    __syncthreads();  // all reads done before ep overwrite

    // transposed epilogue: acc -> ep[s][co] (bf16, stride 72) -> stores
    bf16* ep = dyn;  // 128 x 72 bf16
#pragma unroll
    for (int c = 0; c < 2; c++) {
        if (wm == c) {
#pragma unroll
            for (int im = 0; im < 4; im++) {
                int co_loc = im * 16 + lr;
                int gco = co0 + c * 64 + co_loc;
                float b0v = (gco < Cout) ? bias[gco] : 0.f;
                float b1v = (gco + 8 < Cout) ? bias[gco + 8] : 0.f;
#pragma unroll
                for (int in = 0; in < 4; in++) {
                    int sl = wn * 32 + in * 8 + lc;
                    float* d = acc[im][in];
                    float v0 = d[0] + b0v, v1 = d[1] + b0v;
                    float v2 = d[2] + b1v, v3 = d[3] + b1v;
                    if (RELU) {
                        v0 = fmaxf(v0, 0.f); v1 = fmaxf(v1, 0.f);
                        v2 = fmaxf(v2, 0.f); v3 = fmaxf(v3, 0.f);
                    }
                    ep[sl * 72 + co_loc] = __float2bfloat16(v0);
                    ep[(sl + 1) * 72 + co_loc] = __float2bfloat16(v1);
                    ep[sl * 72 + co_loc + 8] = __float2bfloat16(v2);
                    ep[(sl + 1) * 72 + co_loc + 8] = __float2bfloat16(v3);
                }
            }
        }
        __syncthreads();
        int w = CS - (co0 + c * 64);
        if (w > 64) w = 64;
        if (w > 0) {
            int vpr = w >> 3;
            int tot = 128 * vpr;
            for (int idx = tid; idx < tot; idx += 256) {
                int s = idx / vpr, v = idx - s * vpr;
                if (s0 + s < L)
                    *(uint4*)(outT + ((size_t)b * L + s0 + s) * CS + co0 +
                              c * 64 + v * 8) = *(const uint4*)(ep + s * 72 + v * 8);
            }
        }
        __syncthreads();
    }
}

// ---------------- k squared-norm from kT [b][s][96] -------------------------
__global__ void k2_kernel(const bf16* __restrict__ kT, float* __restrict__ k2) {
    int idx = blockIdx.x * blockDim.x + threadIdx.x;
    if (idx >= BB * SS) return;
    const bf16* p = kT + (size_t)idx * 96;
    float sum = 0.f;
#pragma unroll
    for (int c = 0; c < 96; c++) {
        float v = __bfloat162float(p[c]);
        sum = fmaf(v, v, sum);
    }
    k2[idx] = sum;
}

// ---------------- HMMA attention: qk + log_softmax + prior + mask -----------
// Block: 64 t x 256 s (full S). 8 warps 2x4, warp tile 32t x 64s, K=96 single
// stage. Softmax computed on accumulator fragments.
__global__ __launch_bounds__(256) void attn_mma(
    const bf16* __restrict__ q2T, const bf16* __restrict__ kT,
    const float* __restrict__ k2, const float* __restrict__ prior,
    const int* __restrict__ mask, float* __restrict__ out) {
    constexpr float TEMP = 0.0005f;
    constexpr int RP = 104;  // 96 + 8 pad (row stride 52 words: LDSM-safe)
    extern __shared__ __align__(16) bf16 dynA[];
    bf16* sQ = dynA;                                  // 64 x RP
    bf16* sK = dynA + 64 * RP;                        // 256 x RP
    float* k2s = (float*)(dynA + (64 + 256) * RP);    // 256
    float* redM = k2s + 256;                          // 4 x 64
    float* redS = redM + 256;                         // 4 x 64
    float* lseS = redS + 256;                         // 64

    const int tid = threadIdx.x;
    const int wid = tid >> 5, lane = tid & 31;
    const int wm = wid >> 2, wn = wid & 3;
    const int lr = lane >> 2, qq = lane & 3, lc = qq * 2;
    const int b = blockIdx.y, t0 = blockIdx.x * 64;

    // stage Q (64x96), K (256x96), k2 (256)
#pragma unroll
    for (int n = 0; n < 3; n++) {
        int i = tid + n * 256;
        int row = i / 12, u = i % 12;
        int gt = t0 + row;
        const bf16* src = (gt < TT_TOT)
                              ? q2T + ((size_t)b * TT_TOT + gt) * 96 + u * 8
                              : g_zero;
        cp16(sQ + row * RP + u * 8, src);
    }
#pragma unroll
    for (int n = 0; n < 12; n++) {
        int i = tid + n * 256;
        int row = i / 12, u = i % 12;
        cp16(sK + row * RP + u * 8, kT + ((size_t)b * SS + row) * 96 + u * 8);
    }
    k2s[tid] = k2[b * SS + tid];
    CP_COMMIT();
    CP_WAIT0();
    __syncthreads();

    const int lmA_off = ((lane & 7) + ((lane >> 3) & 1) * 8) * RP +
                        (lane >> 4) * 8;
    const int lmB_off = ((lane & 7) + ((lane >> 4) & 1) * 8) * RP +
                        ((lane >> 3) & 1) * 8;
    const uint32_t aB = smem_u32(sQ + (wm * 32) * RP + lmA_off);
    const uint32_t bB = smem_u32(sK + (wn * 64) * RP + lmB_off);

    float acc[2][8][4];
#pragma unroll
    for (int i = 0; i < 2; i++)
#pragma unroll
        for (int j = 0; j < 8; j++)
#pragma unroll
            for (int v = 0; v < 4; v++) acc[i][j][v] = 0.f;

#pragma unroll
    for (int kk = 0; kk < 6; kk++) {
        uint32_t af[2][4];
#pragma unroll
        for (int im = 0; im < 2; im++)
            ldsm4(af[im][0], af[im][1], af[im][2], af[im][3],
                  aB + (im * 16 * RP + kk * 16) * 2);
        uint32_t bfr[8][2];
#pragma unroll
        for (int h = 0; h < 4; h++)
            ldsm4(bfr[2 * h][0], bfr[2 * h][1], bfr[2 * h + 1][0],
                  bfr[2 * h + 1][1], bB + (h * 16 * RP + kk * 16) * 2);
#pragma unroll
        for (int im = 0; im < 2; im++)
#pragma unroll
            for (int in = 0; in < 8; in++)
                mma16816(acc[im][in], af[im], bfr[in]);
    }

    // logits: a = TEMP*(2*qk - k2[s])  (q2 cancels under log_softmax)
#pragma unroll
    for (int im = 0; im < 2; im++)
#pragma unroll
        for (int in = 0; in < 8; in++) {
            int s = wn * 64 + in * 8 + lc;
            float2 kv = *(float2*)&k2s[s];
            acc[im][in][0] = TEMP * (2.f * acc[im][in][0] - kv.x);
            acc[im][in][1] = TEMP * (2.f * acc[im][in][1] - kv.y);
            acc[im][in][2] = TEMP * (2.f * acc[im][in][2] - kv.x);
            acc[im][in][3] = TEMP * (2.f * acc[im][in][3] - kv.y);
        }

    // per-row (max, sum-exp): thread-local 16 vals -> 4-lane shuffle -> smem
#pragma unroll
    for (int im = 0; im < 2; im++)
#pragma unroll
        for (int h = 0; h < 2; h++) {
            float m = -INFINITY, se = 0.f;
#pragma unroll
            for (int in = 0; in < 8; in++) {
                float v0 = acc[im][in][2 * h], v1 = acc[im][in][2 * h + 1];
                float M = fmaxf(m, fmaxf(v0, v1));
                se = se * __expf(m - M) + __expf(v0 - M) + __expf(v1 - M);
                m = M;
            }
#pragma unroll
            for (int o = 1; o <= 2; o <<= 1) {
                float m2 = __shfl_xor_sync(~0u, m, o);
                float s2 = __shfl_xor_sync(~0u, se, o);
                float M = fmaxf(m, m2);
                se = se * __expf(m - M) + s2 * __expf(m2 - M);
                m = M;
            }
            if (qq == 0) {
                int row = wm * 32 + im * 16 + h * 8 + lr;
                redM[wn * 64 + row] = m;
                redS[wn * 64 + row] = se;
            }
        }
    __syncthreads();
    if (tid < 64) {
        float M = redM[tid], SE = redS[tid];
#pragma unroll
        for (int i = 1; i < 4; i++) {
            float mi = redM[i * 64 + tid], si = redS[i * 64 + tid];
            float Mn = fmaxf(M, mi);
            SE = SE * __expf(M - Mn) + si * __expf(mi - Mn);
            M = Mn;
        }
        lseS[tid] = M + __logf(SE);
    }
    __syncthreads();

    // write-out: a - lse + log(prior + 1e-8), masked
#pragma unroll
    for (int im = 0; im < 2; im++)
#pragma unroll
        for (int h = 0; h < 2; h++) {
            int row = wm * 32 + im * 16 + h * 8 + lr;
            int t = t0 + row;
            if (t < TT_TOT) {
                float lse = lseS[row];
                size_t base = ((size_t)b * TT_TOT + t) * SS;
#pragma unroll
                for (int in = 0; in < 8; in++) {
                    int s = wn * 64 + in * 8 + lc;
                    size_t o = base + s;
                    float2 pr = *(const float2*)&prior[o];
                    int2 mk = *(const int2*)&mask[o];
                    float v0 = acc[im][in][2 * h] - lse + __logf(pr.x + 1e-8f);
                    float v1 = acc[im][in][2 * h + 1] - lse + __logf(pr.y + 1e-8f);
                    float2 res;
                    res.x = mk.x ? v0 : -INFINITY;
                    res.y = mk.y ? v1 : -INFINITY;
                    *(float2*)&out[o] = res;
                }
            }
        }
}

// ---------------- launch ----------------------------------------------------
extern "C" void kernel_launch(void* const* d_in, const int* in_sizes, int n_in,
                              void* d_out, int out_size) {
    const int* phonemes = (const int*)d_in[0];
    const float* mels = (const float*)d_in[1];
    const int* mask = (const int*)d_in[2];
    const float* prior = (const float*)d_in[3];
    const float* emb = (const float*)d_in[4];
    const float* kw[5] = {(const float*)d_in[5], (const float*)d_in[7],
                          (const float*)d_in[9], (const float*)d_in[11],
                          (const float*)d_in[13]};
    const float* kb[5] = {(const float*)d_in[6], (const float*)d_in[8],
                          (const float*)d_in[10], (const float*)d_in[12],
                          (const float*)d_in[14]};
    const float* qw[3] = {(const float*)d_in[15], (const float*)d_in[17],
                          (const float*)d_in[19]};
    const float* qb[3] = {(const float*)d_in[16], (const float*)d_in[18],
                          (const float*)d_in[20]};
    float* out = (float*)d_out;

    bf16 *pA0, *pA1, *pCT, *pKT, *pMT, *pQ0, *pQ1, *pQ2;
    bf16* pw[8];
    float* pk2;
    cudaGetSymbolAddress((void**)&pA0, g_actT0);
    cudaGetSymbolAddress((void**)&pA1, g_actT1);
    cudaGetSymbolAddress((void**)&pCT, g_cT);
    cudaGetSymbolAddress((void**)&pKT, g_kT);
    cudaGetSymbolAddress((void**)&pMT, g_melsT);
    cudaGetSymbolAddress((void**)&pQ0, g_q0T);
    cudaGetSymbolAddress((void**)&pQ1, g_q1T);
    cudaGetSymbolAddress((void**)&pQ2, g_q2T);
    cudaGetSymbolAddress((void**)&pw[0], g_w0);
    cudaGetSymbolAddress((void**)&pw[1], g_w1);
    cudaGetSymbolAddress((void**)&pw[2], g_w2);
    cudaGetSymbolAddress((void**)&pw[3], g_w3);
    cudaGetSymbolAddress((void**)&pw[4], g_w4);
    cudaGetSymbolAddress((void**)&pw[5], g_wq0);
    cudaGetSymbolAddress((void**)&pw[6], g_wq1);
    cudaGetSymbolAddress((void**)&pw[7], g_wq2);
    cudaGetSymbolAddress((void**)&pk2, g_k2v);

    // dynamic smem opt-in (3-stage ring)
    const int SM64 = 3 * 2 * 128 * 72 * 2;   // 110592
    const int SM32 = 3 * 2 * 128 * 40 * 2;   // 61440
    const int SMATT = (64 + 256) * 104 * 2 + (256 * 3 + 64) * 4;  // 69888
    cudaFuncSetAttribute(gemm_conv<5, 512, 64, true>,
                         cudaFuncAttributeMaxDynamicSharedMemorySize, SM64);
    cudaFuncSetAttribute(gemm_conv<3, 512, 64, true>,
                         cudaFuncAttributeMaxDynamicSharedMemorySize, SM64);
    cudaFuncSetAttribute(gemm_conv<1, 1024, 64, false>,
                         cudaFuncAttributeMaxDynamicSharedMemorySize, SM64);
    cudaFuncSetAttribute(gemm_conv<3, 96, 32, true>,
                         cudaFuncAttributeMaxDynamicSharedMemorySize, SM32);
    cudaFuncSetAttribute(gemm_conv<1, 192, 64, true>,
                         cudaFuncAttributeMaxDynamicSharedMemorySize, SM64);
    cudaFuncSetAttribute(gemm_conv<1, 128, 64, false>,
                         cudaFuncAttributeMaxDynamicSharedMemorySize, SM64);
    cudaFuncSetAttribute(attn_mma,
                         cudaFuncAttributeMaxDynamicSharedMemorySize, SMATT);

    // embedding + mels transpose
    embed_kernel<<<(BB * SS * 64 + 255) / 256, 256>>>(phonemes, emb, pA0);
    melsT_kernel<<<dim3(47, 3, BB), 256>>>(mels, pMT);

    // all weight repacks in one launch
    PrepArgs pa;
    const int CoutA[8] = {512, 512, 512, 1024, 80, 160, 80, 80};
    const int CinA[8] = {512, 512, 512, 512, 1024, 80, 160, 80};
    const int KTA[8] = {5, 5, 5, 3, 1, 3, 1, 1};
    const int CINPA[8] = {512, 512, 512, 512, 1024, 96, 192, 128};
    const int RPAD[8] = {512, 512, 512, 1024, 128, 256, 128, 128};
    const float* srcs[8] = {kw[0], kw[1], kw[2], kw[3], kw[4],
                            qw[0], qw[1], qw[2]};
    for (int i = 0; i < 8; i++) {
        pa.src[i] = srcs[i];
        pa.dst[i] = pw[i];
        pa.Cout[i] = CoutA[i];
        pa.Cin[i] = CinA[i];
        pa.KT[i] = KTA[i];
        pa.CINP[i] = CINPA[i];
        pa.total[i] = RPAD[i] * KTA[i] * CINPA[i];
    }
    prep_all<<<dim3(768, 8), 256>>>(pa);

    // ---- key encoder ----
    gemm_conv<5, 512, 64, true><<<dim3(2, 4, BB), 256, SM64>>>(
        pw[0], pA0, kb[0], pA1, 512, 512, SS);
    gemm_conv<5, 512, 64, true><<<dim3(2, 4, BB), 256, SM64>>>(
        pw[1], pA1, kb[1], pA0, 512, 512, SS);
    gemm_conv<5, 512, 64, true><<<dim3(2, 4, BB), 256, SM64>>>(
        pw[2], pA0, kb[2], pA1, 512, 512, SS);
    gemm_conv<3, 512, 64, true><<<dim3(2, 8, BB), 256, SM64>>>(
        pw[3], pA1, kb[3], pCT, 1024, 1024, SS);
    gemm_conv<1, 1024, 64, false><<<dim3(2, 1, BB), 256, SM64>>>(
        pw[4], pCT, kb[4], pKT, 80, 96, SS);

    k2_kernel<<<(BB * SS + 255) / 256, 256>>>(pKT, pk2);

    // ---- query encoder ----
    gemm_conv<3, 96, 32, true><<<dim3(12, 2, BB), 256, SM32>>>(
        pw[5], pMT, qb[0], pQ0, 160, 192, TT_TOT);
    gemm_conv<1, 192, 64, true><<<dim3(12, 1, BB), 256, SM64>>>(
        pw[6], pQ0, qb[1], pQ1, 80, 128, TT_TOT);
    gemm_conv<1, 128, 64, false><<<dim3(12, 1, BB), 256, SM64>>>(
        pw[7], pQ1, qb[2], pQ2, 80, 96, TT_TOT);

    // HMMA attention + log_softmax + prior + mask
    attn_mma<<<dim3((TT_TOT + 63) / 64, BB), 256, SMATT>>>(pQ2, pKT, pk2,
                                                           prior, mask, out);
}